// round 14
// baseline (speedup 1.0000x reference)
#include <cuda_runtime.h>
#include <cuda_bf16.h>
#include <cstdint>
#include <math.h>

#define B_  8
#define S_  2048
#define D_  512
#define NT_ 16          // psum slots per row (S_/128 column tiles)

// ---- GEMM tile config ----
#define BM 128
#define BN 128
#define KC 32
#define NCHUNK (D_/KC)  // 16
#define NSTAGE 3

#define TILE_BYTES 8192

#define STG_A_HI 0
#define STG_A_LO 8192
#define STG_B_HI 16384
#define STG_B_LO 24576
#define STAGE_BYTES 32768
#define SMEM_DYN (2048 + NSTAGE*STAGE_BYTES)   // 100352

// role layout in the 1D fused grid (launch order = dependency order)
#define N_M2T    256
#define N_SPLIT  1024
#define N_PROJ   512
#define N_SCORES 2048
#define ID_SPLIT (N_M2T)
#define ID_PROJ  (N_M2T + N_SPLIT)
#define ID_SCORE (N_M2T + N_SPLIT + N_PROJ)
#define N_GRID   (N_M2T + N_SPLIT + N_PROJ + N_SCORES)

#define N_UTILES 128

// (1/sqrt(512)) * log2(e)
#define EXP2_SCALE 0.06376070918938434f

// ---------------- scratch ----------------
__device__ __nv_bfloat16 g_xhi[B_*S_*D_];
__device__ __nv_bfloat16 g_xlo[B_*S_*D_];
__device__ __nv_bfloat16 g_m2hi[D_*D_];
__device__ __nv_bfloat16 g_m2lo[D_*D_];
__device__ __nv_bfloat16 g_uhi[B_*S_*D_];
__device__ __nv_bfloat16 g_ulo[B_*S_*D_];
__device__ float         g_v2[D_];
__device__ float         g_rk[B_*S_];
__device__ float         g_psum[B_*S_*NT_];
// flags (all self-resetting via reader-count wrap)
__device__ unsigned int  g_xflag[N_UTILES];   // split arrivals (8 per tile)
__device__ unsigned int  g_x_rd[N_UTILES];    // readers wrap 19 (4 proj + 16 scores)
__device__ unsigned int  g_m2flag[4];         // m2t arrivals (64 per tile)
__device__ unsigned int  g_m2_rd[4];          // readers wrap 127
__device__ unsigned int  g_uflag[N_UTILES];   // proj arrivals (4 per tile)
__device__ unsigned int  g_u_rd[N_UTILES];    // readers wrap 15
__device__ unsigned int  g_scnt[N_UTILES];    // scores psum arrivals (16)
__device__ unsigned int  g_srd[N_UTILES];     // readers wrap 15

// ---------------- helpers ----------------
__device__ __forceinline__ uint32_t smem_u32(const void* p) {
    uint32_t a;
    asm("{ .reg .u64 t; cvta.to.shared.u64 t, %1; cvt.u32.u64 %0, t; }" : "=r"(a) : "l"(p));
    return a;
}
__device__ __forceinline__ uint32_t swz64(uint32_t off) {
    return off ^ ((off >> 3) & 0x30);
}
__device__ __forceinline__ void mbar_init(uint32_t m, uint32_t cnt) {
    asm volatile("mbarrier.init.shared.b64 [%0], %1;" :: "r"(m), "r"(cnt) : "memory");
}
__device__ __forceinline__ void mbar_wait(uint32_t m, uint32_t parity) {
    asm volatile(
        "{\n\t.reg .pred P;\n\t"
        "W_%=:\n\t"
        "mbarrier.try_wait.parity.shared::cta.b64 P, [%0], %1, 10000000;\n\t"
        "@P bra.uni D_%=;\n\t"
        "bra.uni W_%=;\n\t"
        "D_%=:\n\t}"
        :: "r"(m), "r"(parity) : "memory");
}
__device__ __forceinline__ void mbar_arrive(uint32_t m) {
    asm volatile("mbarrier.arrive.shared.b64 _, [%0];" :: "r"(m) : "memory");
}
__device__ __forceinline__ void mbar_expect_tx(uint32_t m, uint32_t bytes) {
    asm volatile("mbarrier.arrive.expect_tx.shared.b64 _, [%0], %1;"
                 :: "r"(m), "r"(bytes) : "memory");
}
__device__ __forceinline__ void bulk_g2s(uint32_t dst, const void* src, uint32_t mbar) {
    asm volatile(
        "cp.async.bulk.shared::cluster.global.mbarrier::complete_tx::bytes [%0], [%1], %2, [%3];"
        :: "r"(dst), "l"(src), "r"((uint32_t)TILE_BYTES), "r"(mbar) : "memory");
}
__device__ __forceinline__ void ldsm_x4(uint32_t& r0, uint32_t& r1, uint32_t& r2, uint32_t& r3,
                                        uint32_t addr) {
    asm volatile("ldmatrix.sync.aligned.m8n8.x4.shared.b16 {%0,%1,%2,%3}, [%4];"
                 : "=r"(r0), "=r"(r1), "=r"(r2), "=r"(r3) : "r"(addr));
}
__device__ __forceinline__ void mma16816(float* c, const uint32_t* a, const uint32_t* b) {
    asm volatile(
        "mma.sync.aligned.m16n8k16.row.col.f32.bf16.bf16.f32 "
        "{%0,%1,%2,%3}, {%4,%5,%6,%7}, {%8,%9}, {%0,%1,%2,%3};"
        : "+f"(c[0]), "+f"(c[1]), "+f"(c[2]), "+f"(c[3])
        : "r"(a[0]), "r"(a[1]), "r"(a[2]), "r"(a[3]), "r"(b[0]), "r"(b[1]));
}
__device__ __forceinline__ uint32_t blk_off(int r128, int col) {
    return (uint32_t)(col >> 5) * TILE_BYTES + swz64((uint32_t)(r128*64 + (col & 31)*2));
}
__device__ __forceinline__ void spin_ge(volatile unsigned int* f, unsigned int tgt) {
    while (*f < tgt) __nanosleep(64);
}

// ---------------- v2 pre-kernel ----------------
__global__ __launch_bounds__(256)
void v2_kernel(const float* __restrict__ Wk, const float* __restrict__ bq,
               float* __restrict__ v2)
{
    const int lane = threadIdx.x & 31;
    const int wrow = blockIdx.x * 8 + (threadIdx.x >> 5);
    float s = 0.0f;
    #pragma unroll
    for (int i = 0; i < 16; i++) {
        int d = i*32 + lane;
        s += Wk[(size_t)wrow*D_ + d] * bq[d];
    }
    #pragma unroll
    for (int o = 16; o > 0; o >>= 1) s += __shfl_xor_sync(0xffffffffu, s, o);
    if (lane == 0) v2[wrow] = s;
}

// ---------------- ONE fused kernel: m2t | split | proj | scores ----------------
__global__ __launch_bounds__(256, 2)
void fused_all_kernel(const float* __restrict__ xin,
                      const float* __restrict__ Wk,
                      const float* __restrict__ Wq,
                      const float* __restrict__ v2,
                      float* __restrict__ rk,
                      __nv_bfloat16* __restrict__ xhi,
                      __nv_bfloat16* __restrict__ xlo,
                      __nv_bfloat16* __restrict__ m2hi,
                      __nv_bfloat16* __restrict__ m2lo,
                      __nv_bfloat16* __restrict__ uhi,
                      __nv_bfloat16* __restrict__ ulo,
                      float* __restrict__ outF,
                      float* __restrict__ psum,
                      unsigned int* xflag, unsigned int* x_rd,
                      unsigned int* m2flag, unsigned int* m2_rd,
                      unsigned int* uflag, unsigned int* u_rd,
                      unsigned int* scnt, unsigned int* srd)
{
    extern __shared__ char smem_raw[];
    const int id  = blockIdx.x;
    const int tid = threadIdx.x;

    // ================= role: m2t =================
    if (id < ID_SPLIT) {
        const int g0 = (id >> 4) * 32, f0 = (id & 15) * 32;
        float* sk = reinterpret_cast<float*>(smem_raw);          // 32*33
        float* sq = sk + 32*33;
        const int ty = tid >> 4, tx = tid & 15;
        float a00=0.f, a01=0.f, a10=0.f, a11=0.f;
        for (int d0 = 0; d0 < D_; d0 += 32) {
            #pragma unroll
            for (int p = 0; p < 4; p++) {
                int e = p*256 + tid;
                int r = e >> 5, c = e & 31;
                sk[r*33+c] = Wk[(size_t)(g0+r)*D_ + d0 + c];
                sq[r*33+c] = Wq[(size_t)(f0+r)*D_ + d0 + c];
            }
            __syncthreads();
            #pragma unroll
            for (int d = 0; d < 32; d++) {
                float k0v = sk[(2*ty)*33+d], k1v = sk[(2*ty+1)*33+d];
                float q0v = sq[(2*tx)*33+d], q1v = sq[(2*tx+1)*33+d];
                a00 = fmaf(k0v, q0v, a00); a01 = fmaf(k0v, q1v, a01);
                a10 = fmaf(k1v, q0v, a10); a11 = fmaf(k1v, q1v, a11);
            }
            __syncthreads();
        }
        float av[2][2] = {{a00,a01},{a10,a11}};
        #pragma unroll
        for (int i = 0; i < 2; i++)
            #pragma unroll
            for (int j = 0; j < 2; j++) {
                float v = av[i][j];
                __nv_bfloat16 h = __float2bfloat16(v);
                __nv_bfloat16 l = __float2bfloat16(v - __bfloat162float(h));
                int gg = g0 + 2*ty + i;
                int ff = f0 + 2*tx + j;
                size_t tbase = ((size_t)(gg >> 7) * 16) * TILE_BYTES;
                uint32_t off = blk_off(gg & 127, ff);
                *reinterpret_cast<__nv_bfloat16*>((char*)m2hi + tbase + off) = h;
                *reinterpret_cast<__nv_bfloat16*>((char*)m2lo + tbase + off) = l;
            }
        __threadfence();
        __syncthreads();
        if (tid == 0) atomicAdd(&m2flag[g0 >> 7], 1u);
        return;
    }

    // ================= role: split x =================
    if (id < ID_PROJ) {
        const int s2  = id - ID_SPLIT;
        const int row = s2*16 + (tid >> 4);
        const int c0  = (tid & 15) * 32;
        const float* src = xin + (size_t)row * D_ + c0;
        float f[32];
        #pragma unroll
        for (int j = 0; j < 8; j++)
            *reinterpret_cast<float4*>(f + j*4) = reinterpret_cast<const float4*>(src)[j];
        __nv_bfloat16 h[32], l[32];
        #pragma unroll
        for (int j = 0; j < 32; j++) {
            h[j] = __float2bfloat16(f[j]);
            l[j] = __float2bfloat16(f[j] - __bfloat162float(h[j]));
        }
        const size_t tbase = ((size_t)(row >> 7) * 16) * TILE_BYTES;
        #pragma unroll
        for (int gq = 0; gq < 4; gq++) {
            uint32_t off = blk_off(row & 127, c0 + gq*8);
            *reinterpret_cast<uint4*>((char*)xhi + tbase + off) = *reinterpret_cast<uint4*>(h + gq*8);
            *reinterpret_cast<uint4*>((char*)xlo + tbase + off) = *reinterpret_cast<uint4*>(l + gq*8);
        }
        const float* w = v2 + c0;
        float local = 0.f;
        #pragma unroll
        for (int j = 0; j < 32; j++) local += f[j] * w[j];
        #pragma unroll
        for (int o = 8; o > 0; o >>= 1) local += __shfl_xor_sync(0xffffffffu, local, o);
        if ((tid & 15) == 0) rk[row] = local * EXP2_SCALE;
        __threadfence();
        __syncthreads();
        if (tid == 0) atomicAdd(&xflag[s2 >> 3], 1u);
        return;
    }

    // ================= roles: proj / scores GEMM =================
    const uint32_t sb = (smem_u32(smem_raw) + 1023u) & ~1023u;
    __shared__ float s_rowsum[128][4];
    __shared__ float s_inv[128];

    const int lane   = tid & 31;
    const int wid    = tid >> 5;
    const int warp_m = wid & 1;
    const int warp_n = wid >> 1;
    const bool isProj = (id < ID_SCORE);

    int atile, btile, arow0, ncol0, sbx = 0, sbz = 0;
    const __nv_bfloat16 *aHiT, *aLoT, *bHiT, *bLoT;
    if (isProj) {
        const int p = id - ID_PROJ;
        const int bx = p & 3, by = p >> 2;
        atile = by; btile = bx;
        arow0 = by * BM; ncol0 = bx * BN;
        aHiT = xhi;  aLoT = xlo;  bHiT = m2hi; bLoT = m2lo;
    } else {
        const int sid = id - ID_SCORE;
        sbx = sid & 15;
        const int sby = (sid >> 4) & 15;
        sbz = sid >> 8;
        atile = sbz * 16 + sby;
        btile = sbz * 16 + sbx;
        arow0 = atile * BM; ncol0 = sbx * BN;
        aHiT = uhi;  aLoT = ulo;  bHiT = xhi;  bLoT = xlo;
    }
    const char* aHiB = (const char*)aHiT + (size_t)atile * 16 * TILE_BYTES;
    const char* aLoB = (const char*)aLoT + (size_t)atile * 16 * TILE_BYTES;
    const char* bHiB = (const char*)bHiT + (size_t)btile * 16 * TILE_BYTES;
    const char* bLoB = (const char*)bLoT + (size_t)btile * 16 * TILE_BYTES;
    const float* rkb = rk + (size_t)sbz * S_;

    if (tid == 0) {
        #pragma unroll
        for (int s = 0; s < NSTAGE; s++) {
            mbar_init(sb + s*8, 1);
            mbar_init(sb + 24 + s*8, 8);
        }
    }
    __syncthreads();

    // producer prologue: wait for input tiles, then issue chunks 0,1
    if (tid == 0) {
        if (isProj) {
            spin_ge(xflag + atile, 8u);
            spin_ge(m2flag + btile, 64u);
            __threadfence();
            if (atomicInc(&x_rd[atile], 19u) == 19u)  xflag[atile] = 0u;
            if (atomicInc(&m2_rd[btile], 127u) == 127u) m2flag[btile] = 0u;
        } else {
            spin_ge(uflag + atile, 4u);
            spin_ge(xflag + btile, 8u);
            __threadfence();
            if (atomicInc(&u_rd[atile], 15u) == 15u) uflag[atile] = 0u;
            if (atomicInc(&x_rd[btile], 19u) == 19u) xflag[btile] = 0u;
        }
        #pragma unroll
        for (int i = 0; i < 2; i++) {
            uint32_t st = sb + 1024 + i*STAGE_BYTES;
            uint32_t mb = sb + i*8;
            mbar_expect_tx(mb, STAGE_BYTES);
            bulk_g2s(st + STG_A_HI, aHiB + (size_t)i*TILE_BYTES, mb);
            bulk_g2s(st + STG_A_LO, aLoB + (size_t)i*TILE_BYTES, mb);
            bulk_g2s(st + STG_B_HI, bHiB + (size_t)i*TILE_BYTES, mb);
            bulk_g2s(st + STG_B_LO, bLoB + (size_t)i*TILE_BYTES, mb);
        }
    }

    const int laneR = lane & 15;
    const uint32_t laneC = (uint32_t)(lane >> 4) * 16;
    const uint32_t xorM  = (uint32_t)(laneR & 6) << 3;
    const uint32_t aBase = (uint32_t)(warp_m*64 + laneR) * 64;
    const uint32_t bBase = (uint32_t)(warp_n*32 + laneR) * 64;

    float acc[4][4][4];
    #pragma unroll
    for (int i = 0; i < 4; i++)
        #pragma unroll
        for (int j = 0; j < 4; j++)
            #pragma unroll
            for (int k = 0; k < 4; k++) acc[i][j][k] = 0.0f;

    int stage_c = 0;
    for (int c = 0; c < NCHUNK; c++) {
        mbar_wait(sb + stage_c*8, (c/NSTAGE) & 1);

        if (tid == 0 && c + 2 < NCHUNK) {
            const int i = c + 2;
            int si = stage_c + 2; if (si >= NSTAGE) si -= NSTAGE;
            if (i >= NSTAGE)
                mbar_wait(sb + 24 + si*8, ((i/NSTAGE) - 1) & 1);
            uint32_t st = sb + 1024 + si*STAGE_BYTES;
            uint32_t mb = sb + si*8;
            mbar_expect_tx(mb, STAGE_BYTES);
            bulk_g2s(st + STG_A_HI, aHiB + (size_t)i*TILE_BYTES, mb);
            bulk_g2s(st + STG_A_LO, aLoB + (size_t)i*TILE_BYTES, mb);
            bulk_g2s(st + STG_B_HI, bHiB + (size_t)i*TILE_BYTES, mb);
            bulk_g2s(st + STG_B_LO, bLoB + (size_t)i*TILE_BYTES, mb);
        }

        const uint32_t stage = sb + 1024 + stage_c*STAGE_BYTES;
        #pragma unroll
        for (int kk = 0; kk < 2; kk++) {
            const uint32_t kbx = ((uint32_t)kk*32 + laneC) ^ xorM;

            uint32_t bhiF[4][2], bloF[4][2];
            #pragma unroll
            for (int g = 0; g < 2; g++) {
                uint32_t off = bBase + (uint32_t)g*1024 + kbx;
                uint32_t t0, t1, t2, t3;
                ldsm_x4(t0, t1, t2, t3, stage + STG_B_HI + off);
                bhiF[2*g][0] = t0; bhiF[2*g][1] = t2; bhiF[2*g+1][0] = t1; bhiF[2*g+1][1] = t3;
                ldsm_x4(t0, t1, t2, t3, stage + STG_B_LO + off);
                bloF[2*g][0] = t0; bloF[2*g][1] = t2; bloF[2*g+1][0] = t1; bloF[2*g+1][1] = t3;
            }
            uint32_t ahiF[2][4], aloF[2][4];
            {
                uint32_t off = aBase + kbx;
                ldsm_x4(ahiF[0][0], ahiF[0][1], ahiF[0][2], ahiF[0][3], stage + STG_A_HI + off);
                ldsm_x4(aloF[0][0], aloF[0][1], aloF[0][2], aloF[0][3], stage + STG_A_LO + off);
            }
            #pragma unroll
            for (int mf = 0; mf < 4; mf++) {
                const int cur = mf & 1, nxt = cur ^ 1;
                if (mf < 3) {
                    uint32_t off = aBase + (uint32_t)(mf+1)*1024 + kbx;
                    ldsm_x4(ahiF[nxt][0], ahiF[nxt][1], ahiF[nxt][2], ahiF[nxt][3],
                            stage + STG_A_HI + off);
                    ldsm_x4(aloF[nxt][0], aloF[nxt][1], aloF[nxt][2], aloF[nxt][3],
                            stage + STG_A_LO + off);
                }
                if (kk == 1 && mf == 3 && lane == 0)
                    mbar_arrive(sb + 24 + stage_c*8);
                #pragma unroll
                for (int nf = 0; nf < 4; nf++)
                    mma16816(acc[mf][nf], ahiF[cur], bhiF[nf]);
                #pragma unroll
                for (int nf = 0; nf < 4; nf++)
                    mma16816(acc[mf][nf], ahiF[cur], bloF[nf]);
                #pragma unroll
                for (int nf = 0; nf < 4; nf++)
                    mma16816(acc[mf][nf], aloF[cur], bhiF[nf]);
            }
        }
        stage_c++; if (stage_c >= NSTAGE) stage_c -= NSTAGE;
    }

    // ---- epilogue ----
    const int g = lane >> 2, q = lane & 3;

    if (!isProj) {
        float rs[8];
        #pragma unroll
        for (int i = 0; i < 8; i++) rs[i] = 0.0f;
        #pragma unroll
        for (int mf = 0; mf < 4; mf++) {
            #pragma unroll
            for (int nf = 0; nf < 4; nf++) {
                const int col = ncol0 + warp_n*32 + nf*8 + q*2;
                const float r0 = __ldg(&rkb[col]);
                const float r1 = __ldg(&rkb[col+1]);
                acc[mf][nf][0] = exp2f(fmaf(acc[mf][nf][0], EXP2_SCALE, r0));
                acc[mf][nf][1] = exp2f(fmaf(acc[mf][nf][1], EXP2_SCALE, r1));
                acc[mf][nf][2] = exp2f(fmaf(acc[mf][nf][2], EXP2_SCALE, r0));
                acc[mf][nf][3] = exp2f(fmaf(acc[mf][nf][3], EXP2_SCALE, r1));
                rs[mf*2 + 0] += acc[mf][nf][0] + acc[mf][nf][1];
                rs[mf*2 + 1] += acc[mf][nf][2] + acc[mf][nf][3];
            }
        }
        #pragma unroll
        for (int i = 0; i < 8; i++) {
            rs[i] += __shfl_xor_sync(0xffffffffu, rs[i], 1);
            rs[i] += __shfl_xor_sync(0xffffffffu, rs[i], 2);
        }
        if (q == 0) {
            #pragma unroll
            for (int i = 0; i < 8; i++)
                s_rowsum[warp_m*64 + (i>>1)*16 + (i&1)*8 + g][warp_n] = rs[i];
        }
        __syncthreads();
        if (tid < 128) {
            float s = s_rowsum[tid][0] + s_rowsum[tid][1] + s_rowsum[tid][2] + s_rowsum[tid][3];
            psum[((size_t)arow0 + tid)*NT_ + sbx] = s;
        }

        __threadfence();
        __syncthreads();
        if (tid == 0) {
            atomicAdd(&scnt[atile], 1u);
            spin_ge(scnt + atile, (unsigned)NT_);
        }
        __syncthreads();
        __threadfence();
        if (tid < 128) {
            const float* pr = &psum[((size_t)arow0 + tid) * NT_];
            float s = 0.0f;
            #pragma unroll
            for (int t = 0; t < NT_; t++) s += pr[t];
            s_inv[tid] = 1.0f / s;
        }
        __syncthreads();

        #pragma unroll
        for (int mf = 0; mf < 4; mf++) {
            const int r0 = warp_m*64 + mf*16 + g;
            const float iv0 = s_inv[r0];
            const float iv1 = s_inv[r0 + 8];
            const size_t grow = (size_t)arow0 + r0;
            #pragma unroll
            for (int nf = 0; nf < 4; nf++) {
                const int col = ncol0 + warp_n*32 + nf*8 + q*2;
                *reinterpret_cast<float2*>(&outF[grow*S_ + col]) =
                    make_float2(acc[mf][nf][0]*iv0, acc[mf][nf][1]*iv0);
                *reinterpret_cast<float2*>(&outF[(grow+8)*S_ + col]) =
                    make_float2(acc[mf][nf][2]*iv1, acc[mf][nf][3]*iv1);
            }
        }

        if (tid == 0) {
            unsigned int old = atomicInc(&srd[atile], 15u);
            if (old == 15u) scnt[atile] = 0u;
        }
    } else {
        char* oh = (char*)uhi + (size_t)atile * 16 * TILE_BYTES;
        char* ol = (char*)ulo + (size_t)atile * 16 * TILE_BYTES;
        #pragma unroll
        for (int mf = 0; mf < 4; mf++) {
            const int r0 = warp_m*64 + mf*16 + g;
            #pragma unroll
            for (int nf = 0; nf < 4; nf++) {
                const int col = ncol0 + warp_n*32 + nf*8 + q*2;
                float v0 = acc[mf][nf][0];
                float v1 = acc[mf][nf][1];
                float v2v = acc[mf][nf][2];
                float v3 = acc[mf][nf][3];
                __nv_bfloat162 h01, l01, h23, l23;
                h01.x = __float2bfloat16(v0); h01.y = __float2bfloat16(v1);
                l01.x = __float2bfloat16(v0 - __bfloat162float(h01.x));
                l01.y = __float2bfloat16(v1 - __bfloat162float(h01.y));
                h23.x = __float2bfloat16(v2v); h23.y = __float2bfloat16(v3);
                l23.x = __float2bfloat16(v2v - __bfloat162float(h23.x));
                l23.y = __float2bfloat16(v3 - __bfloat162float(h23.y));
                uint32_t o0 = blk_off(r0,     col);
                uint32_t o1 = blk_off(r0 + 8, col);
                *reinterpret_cast<__nv_bfloat162*>(oh + o0) = h01;
                *reinterpret_cast<__nv_bfloat162*>(ol + o0) = l01;
                *reinterpret_cast<__nv_bfloat162*>(oh + o1) = h23;
                *reinterpret_cast<__nv_bfloat162*>(ol + o1) = l23;
            }
        }
        __threadfence();
        __syncthreads();
        if (tid == 0) atomicAdd(&uflag[atile], 1u);
    }
}

// ---------------- launcher ----------------
extern "C" void kernel_launch(void* const* d_in, const int* in_sizes, int n_in,
                              void* d_out, int out_size)
{
    const float* x  = (const float*)d_in[0];
    const float* Wq = (const float*)d_in[1];
    const float* bq = (const float*)d_in[2];
    const float* Wk = (const float*)d_in[3];
    float* out = (float*)d_out;

    __nv_bfloat16 *xhi, *xlo, *m2hi, *m2lo, *uhi, *ulo;
    float *v2p, *rkp, *pptr;
    unsigned int *xflagp, *xrdp, *m2flagp, *m2rdp, *uflagp, *urdp, *scntp, *srdp;
    cudaGetSymbolAddress((void**)&xhi,  g_xhi);
    cudaGetSymbolAddress((void**)&xlo,  g_xlo);
    cudaGetSymbolAddress((void**)&m2hi, g_m2hi);
    cudaGetSymbolAddress((void**)&m2lo, g_m2lo);
    cudaGetSymbolAddress((void**)&uhi,  g_uhi);
    cudaGetSymbolAddress((void**)&ulo,  g_ulo);
    cudaGetSymbolAddress((void**)&v2p,  g_v2);
    cudaGetSymbolAddress((void**)&rkp,  g_rk);
    cudaGetSymbolAddress((void**)&pptr, g_psum);
    cudaGetSymbolAddress((void**)&xflagp, g_xflag);
    cudaGetSymbolAddress((void**)&xrdp,   g_x_rd);
    cudaGetSymbolAddress((void**)&m2flagp, g_m2flag);
    cudaGetSymbolAddress((void**)&m2rdp,   g_m2_rd);
    cudaGetSymbolAddress((void**)&uflagp, g_uflag);
    cudaGetSymbolAddress((void**)&urdp,   g_u_rd);
    cudaGetSymbolAddress((void**)&scntp,  g_scnt);
    cudaGetSymbolAddress((void**)&srdp,   g_srd);

    cudaFuncSetAttribute(fused_all_kernel, cudaFuncAttributeMaxDynamicSharedMemorySize, SMEM_DYN);

    // 1) v2 = Wk @ bq (tiny; rk in the fused kernel depends on it)
    v2_kernel<<<D_/8, 256>>>(Wk, bq, v2p);

    // 2) everything else in ONE launch: m2t | split_x | proj | scores+softmax
    fused_all_kernel<<<N_GRID, 256, SMEM_DYN>>>(
        x, Wk, Wq, v2p, rkp, xhi, xlo, m2hi, m2lo, uhi, ulo, out, pptr,
        xflagp, xrdp, m2flagp, m2rdp, uflagp, urdp, scntp, srdp);
}

// round 15
// speedup vs baseline: 1.0170x; 1.0170x over previous
#include <cuda_runtime.h>
#include <cuda_bf16.h>
#include <cstdint>
#include <math.h>

#define B_  8
#define S_  2048
#define D_  512
#define NT_ 16          // psum slots per row (S_/128 column tiles)

// ---- GEMM tile config ----
#define BM 128
#define BN 128
#define KC 32
#define NCHUNK (D_/KC)  // 16
#define NSTAGE 3

#define TILE_BYTES 8192

#define STG_A_HI 0
#define STG_A_LO 8192
#define STG_B_HI 16384
#define STG_B_LO 24576
#define STAGE_BYTES 32768
#define SMEM_DYN (2048 + NSTAGE*STAGE_BYTES)   // 100352

#define N_PROJ_CTAS 512      // proj role: ids [0, 512)
#define N_UTILES    128

// prep kernel roles
#define PREP_V2    64
#define PREP_M2T   256
#define PREP_SPLIT 1024
#define PREP_GRID  (PREP_V2 + PREP_M2T + PREP_SPLIT)   // 1344
#define PREP_SMEM  (2*32*33*4)                          // 8448

// (1/sqrt(512)) * log2(e)
#define EXP2_SCALE 0.06376070918938434f

// ---------------- scratch ----------------
__device__ __nv_bfloat16 g_xhi[B_*S_*D_];
__device__ __nv_bfloat16 g_xlo[B_*S_*D_];
__device__ __nv_bfloat16 g_m2hi[D_*D_];
__device__ __nv_bfloat16 g_m2lo[D_*D_];
__device__ __nv_bfloat16 g_uhi[B_*S_*D_];
__device__ __nv_bfloat16 g_ulo[B_*S_*D_];
__device__ float         g_v2[D_];
__device__ float         g_rk[B_*S_];
__device__ float         g_psum[B_*S_*NT_];
__device__ unsigned int  g_v2flag;            // v2 arrivals (64); reset by last split reader
__device__ unsigned int  g_v2rd;              // split reader counter (wrap 1023)
__device__ unsigned int  g_uflag[N_UTILES];   // proj arrivals (4 per tile)
__device__ unsigned int  g_u_rd[N_UTILES];    // readers wrap 15
__device__ unsigned int  g_scnt[N_UTILES];    // scores psum arrivals (16)
__device__ unsigned int  g_srd[N_UTILES];     // readers wrap 15

// ---------------- helpers ----------------
__device__ __forceinline__ uint32_t smem_u32(const void* p) {
    uint32_t a;
    asm("{ .reg .u64 t; cvta.to.shared.u64 t, %1; cvt.u32.u64 %0, t; }" : "=r"(a) : "l"(p));
    return a;
}
__device__ __forceinline__ uint32_t swz64(uint32_t off) {
    return off ^ ((off >> 3) & 0x30);
}
__device__ __forceinline__ void mbar_init(uint32_t m, uint32_t cnt) {
    asm volatile("mbarrier.init.shared.b64 [%0], %1;" :: "r"(m), "r"(cnt) : "memory");
}
__device__ __forceinline__ void mbar_wait(uint32_t m, uint32_t parity) {
    asm volatile(
        "{\n\t.reg .pred P;\n\t"
        "W_%=:\n\t"
        "mbarrier.try_wait.parity.shared::cta.b64 P, [%0], %1, 10000000;\n\t"
        "@P bra.uni D_%=;\n\t"
        "bra.uni W_%=;\n\t"
        "D_%=:\n\t}"
        :: "r"(m), "r"(parity) : "memory");
}
__device__ __forceinline__ void mbar_arrive(uint32_t m) {
    asm volatile("mbarrier.arrive.shared.b64 _, [%0];" :: "r"(m) : "memory");
}
__device__ __forceinline__ void mbar_expect_tx(uint32_t m, uint32_t bytes) {
    asm volatile("mbarrier.arrive.expect_tx.shared.b64 _, [%0], %1;"
                 :: "r"(m), "r"(bytes) : "memory");
}
__device__ __forceinline__ void bulk_g2s(uint32_t dst, const void* src, uint32_t mbar) {
    asm volatile(
        "cp.async.bulk.shared::cluster.global.mbarrier::complete_tx::bytes [%0], [%1], %2, [%3];"
        :: "r"(dst), "l"(src), "r"((uint32_t)TILE_BYTES), "r"(mbar) : "memory");
}
__device__ __forceinline__ void ldsm_x4(uint32_t& r0, uint32_t& r1, uint32_t& r2, uint32_t& r3,
                                        uint32_t addr) {
    asm volatile("ldmatrix.sync.aligned.m8n8.x4.shared.b16 {%0,%1,%2,%3}, [%4];"
                 : "=r"(r0), "=r"(r1), "=r"(r2), "=r"(r3) : "r"(addr));
}
__device__ __forceinline__ void mma16816(float* c, const uint32_t* a, const uint32_t* b) {
    asm volatile(
        "mma.sync.aligned.m16n8k16.row.col.f32.bf16.bf16.f32 "
        "{%0,%1,%2,%3}, {%4,%5,%6,%7}, {%8,%9}, {%0,%1,%2,%3};"
        : "+f"(c[0]), "+f"(c[1]), "+f"(c[2]), "+f"(c[3])
        : "r"(a[0]), "r"(a[1]), "r"(a[2]), "r"(a[3]), "r"(b[0]), "r"(b[1]));
}
__device__ __forceinline__ uint32_t blk_off(int r128, int col) {
    return (uint32_t)(col >> 5) * TILE_BYTES + swz64((uint32_t)(r128*64 + (col & 31)*2));
}
__device__ __forceinline__ void spin_ge(volatile unsigned int* f, unsigned int tgt) {
    while (*f < tgt) __nanosleep(64);
}

// ---------------- ONE prep kernel: v2 | m2t | split (co-resident) ----------
__global__ __launch_bounds__(256)
void prep_kernel(const float* __restrict__ xin,
                 const float* __restrict__ Wk,
                 const float* __restrict__ Wq,
                 const float* __restrict__ bq,
                 float* __restrict__ v2,
                 float* __restrict__ rk,
                 __nv_bfloat16* __restrict__ xhi,
                 __nv_bfloat16* __restrict__ xlo,
                 __nv_bfloat16* __restrict__ m2hi,
                 __nv_bfloat16* __restrict__ m2lo,
                 unsigned int* v2flag, unsigned int* v2rd)
{
    extern __shared__ char smem_raw[];
    const int id  = blockIdx.x;
    const int tid = threadIdx.x;

    // ---- role: v2 = Wk @ bq (64 CTAs x 8 rows) ----
    if (id < PREP_V2) {
        const int lane = tid & 31;
        const int wrow = id * 8 + (tid >> 5);
        float s = 0.0f;
        #pragma unroll
        for (int i = 0; i < 16; i++) {
            int d = i*32 + lane;
            s += Wk[(size_t)wrow*D_ + d] * bq[d];
        }
        #pragma unroll
        for (int o = 16; o > 0; o >>= 1) s += __shfl_xor_sync(0xffffffffu, s, o);
        if (lane == 0) v2[wrow] = s;
        __threadfence();
        __syncthreads();
        if (tid == 0) atomicAdd(v2flag, 1u);
        return;
    }

    // ---- role: m2t[g,f] = sum_d Wk[g,d]*Wq[f,d], bf16 hi/lo BLOCKED ----
    if (id < PREP_V2 + PREP_M2T) {
        const int m = id - PREP_V2;
        const int g0 = (m >> 4) * 32, f0 = (m & 15) * 32;
        float* sk = reinterpret_cast<float*>(smem_raw);   // 32*33
        float* sq = sk + 32*33;
        const int ty = tid >> 4, tx = tid & 15;
        float a00=0.f, a01=0.f, a10=0.f, a11=0.f;
        for (int d0 = 0; d0 < D_; d0 += 32) {
            #pragma unroll
            for (int p = 0; p < 4; p++) {
                int e = p*256 + tid;
                int r = e >> 5, c = e & 31;
                sk[r*33+c] = Wk[(size_t)(g0+r)*D_ + d0 + c];
                sq[r*33+c] = Wq[(size_t)(f0+r)*D_ + d0 + c];
            }
            __syncthreads();
            #pragma unroll
            for (int d = 0; d < 32; d++) {
                float k0v = sk[(2*ty)*33+d], k1v = sk[(2*ty+1)*33+d];
                float q0v = sq[(2*tx)*33+d], q1v = sq[(2*tx+1)*33+d];
                a00 = fmaf(k0v, q0v, a00); a01 = fmaf(k0v, q1v, a01);
                a10 = fmaf(k1v, q0v, a10); a11 = fmaf(k1v, q1v, a11);
            }
            __syncthreads();
        }
        float av[2][2] = {{a00,a01},{a10,a11}};
        #pragma unroll
        for (int i = 0; i < 2; i++)
            #pragma unroll
            for (int j = 0; j < 2; j++) {
                float v = av[i][j];
                __nv_bfloat16 h = __float2bfloat16(v);
                __nv_bfloat16 l = __float2bfloat16(v - __bfloat162float(h));
                int gg = g0 + 2*ty + i;
                int ff = f0 + 2*tx + j;
                size_t tbase = ((size_t)(gg >> 7) * 16) * TILE_BYTES;
                uint32_t off = blk_off(gg & 127, ff);
                *reinterpret_cast<__nv_bfloat16*>((char*)m2hi + tbase + off) = h;
                *reinterpret_cast<__nv_bfloat16*>((char*)m2lo + tbase + off) = l;
            }
        return;
    }

    // ---- role: split x into bf16 hi/lo BLOCKED + rk (needs v2) ----
    {
        const int s2  = id - (PREP_V2 + PREP_M2T);
        if (tid == 0) spin_ge(v2flag, (unsigned)PREP_V2);
        __syncthreads();
        __threadfence();                       // acquire v2 stores

        const int row = s2*16 + (tid >> 4);
        const int c0  = (tid & 15) * 32;
        const float* src = xin + (size_t)row * D_ + c0;
        float f[32];
        #pragma unroll
        for (int j = 0; j < 8; j++)
            *reinterpret_cast<float4*>(f + j*4) = reinterpret_cast<const float4*>(src)[j];
        __nv_bfloat16 h[32], l[32];
        #pragma unroll
        for (int j = 0; j < 32; j++) {
            h[j] = __float2bfloat16(f[j]);
            l[j] = __float2bfloat16(f[j] - __bfloat162float(h[j]));
        }
        const size_t tbase = ((size_t)(row >> 7) * 16) * TILE_BYTES;
        #pragma unroll
        for (int gq = 0; gq < 4; gq++) {
            uint32_t off = blk_off(row & 127, c0 + gq*8);
            *reinterpret_cast<uint4*>((char*)xhi + tbase + off) = *reinterpret_cast<uint4*>(h + gq*8);
            *reinterpret_cast<uint4*>((char*)xlo + tbase + off) = *reinterpret_cast<uint4*>(l + gq*8);
        }
        const float* w = v2 + c0;
        float local = 0.f;
        #pragma unroll
        for (int j = 0; j < 32; j++) local += f[j] * w[j];
        #pragma unroll
        for (int o = 8; o > 0; o >>= 1) local += __shfl_xor_sync(0xffffffffu, local, o);
        if ((tid & 15) == 0) rk[row] = local * EXP2_SCALE;

        // self-reset of v2flag for graph replay (last of 1024 readers)
        if (tid == 0) {
            unsigned int old = atomicInc(v2rd, (unsigned)PREP_SPLIT - 1u);
            if (old == (unsigned)PREP_SPLIT - 1u) *v2flag = 0u;
        }
    }
}

// ---------------- fused proj+scores+softmax NT GEMM (R13, unchanged) --------
__global__ __launch_bounds__(256, 2)
void fused_gemm_kernel(const __nv_bfloat16* __restrict__ xhi,
                       const __nv_bfloat16* __restrict__ xlo,
                       const __nv_bfloat16* __restrict__ m2hi,
                       const __nv_bfloat16* __restrict__ m2lo,
                       __nv_bfloat16* __restrict__ uhi,
                       __nv_bfloat16* __restrict__ ulo,
                       const float* __restrict__ rk,
                       float* __restrict__ outF,
                       float* __restrict__ psum,
                       unsigned int* uflag,
                       unsigned int* rcnt,
                       unsigned int* scnt,
                       unsigned int* srd)
{
    extern __shared__ char smem_raw[];
    const uint32_t sb = (smem_u32(smem_raw) + 1023u) & ~1023u;
    __shared__ float s_rowsum[128][4];
    __shared__ float s_inv[128];

    const int id     = blockIdx.x;
    const bool isProj = (id < N_PROJ_CTAS);
    const int tid    = threadIdx.x;
    const int lane   = tid & 31;
    const int wid    = tid >> 5;
    const int warp_m = wid & 1;
    const int warp_n = wid >> 1;

    int atile, btile, arow0, ncol0, sbx = 0, sbz = 0;
    const __nv_bfloat16 *aHiT, *aLoT, *bHiT, *bLoT;
    if (isProj) {
        const int bx = id & 3, by = id >> 2;
        atile = by; btile = bx;
        arow0 = by * BM; ncol0 = bx * BN;
        aHiT = xhi;  aLoT = xlo;  bHiT = m2hi; bLoT = m2lo;
    } else {
        const int sid = id - N_PROJ_CTAS;
        sbx = sid & 15;
        const int sby = (sid >> 4) & 15;
        sbz = sid >> 8;
        atile = sbz * 16 + sby;
        btile = sbz * 16 + sbx;
        arow0 = atile * BM; ncol0 = sbx * BN;
        aHiT = uhi;  aLoT = ulo;  bHiT = xhi;  bLoT = xlo;
    }
    const char* aHiB = (const char*)aHiT + (size_t)atile * 16 * TILE_BYTES;
    const char* aLoB = (const char*)aLoT + (size_t)atile * 16 * TILE_BYTES;
    const char* bHiB = (const char*)bHiT + (size_t)btile * 16 * TILE_BYTES;
    const char* bLoB = (const char*)bLoT + (size_t)btile * 16 * TILE_BYTES;
    const float* rkb = rk + (size_t)sbz * S_;

    if (tid == 0) {
        #pragma unroll
        for (int s = 0; s < NSTAGE; s++) {
            mbar_init(sb + s*8, 1);
            mbar_init(sb + 24 + s*8, 8);
        }
    }
    __syncthreads();

    if (tid == 0) {
        if (!isProj) {
            spin_ge(uflag + atile, 4u);
            __threadfence();
            unsigned int old = atomicInc(&rcnt[atile], 15u);
            if (old == 15u) uflag[atile] = 0u;
        }
        #pragma unroll
        for (int i = 0; i < 2; i++) {
            uint32_t st = sb + 1024 + i*STAGE_BYTES;
            uint32_t mb = sb + i*8;
            mbar_expect_tx(mb, STAGE_BYTES);
            bulk_g2s(st + STG_A_HI, aHiB + (size_t)i*TILE_BYTES, mb);
            bulk_g2s(st + STG_A_LO, aLoB + (size_t)i*TILE_BYTES, mb);
            bulk_g2s(st + STG_B_HI, bHiB + (size_t)i*TILE_BYTES, mb);
            bulk_g2s(st + STG_B_LO, bLoB + (size_t)i*TILE_BYTES, mb);
        }
    }

    const int laneR = lane & 15;
    const uint32_t laneC = (uint32_t)(lane >> 4) * 16;
    const uint32_t xorM  = (uint32_t)(laneR & 6) << 3;
    const uint32_t aBase = (uint32_t)(warp_m*64 + laneR) * 64;
    const uint32_t bBase = (uint32_t)(warp_n*32 + laneR) * 64;

    float acc[4][4][4];
    #pragma unroll
    for (int i = 0; i < 4; i++)
        #pragma unroll
        for (int j = 0; j < 4; j++)
            #pragma unroll
            for (int k = 0; k < 4; k++) acc[i][j][k] = 0.0f;

    int stage_c = 0;
    for (int c = 0; c < NCHUNK; c++) {
        mbar_wait(sb + stage_c*8, (c/NSTAGE) & 1);

        if (tid == 0 && c + 2 < NCHUNK) {
            const int i = c + 2;
            int si = stage_c + 2; if (si >= NSTAGE) si -= NSTAGE;
            if (i >= NSTAGE)
                mbar_wait(sb + 24 + si*8, ((i/NSTAGE) - 1) & 1);
            uint32_t st = sb + 1024 + si*STAGE_BYTES;
            uint32_t mb = sb + si*8;
            mbar_expect_tx(mb, STAGE_BYTES);
            bulk_g2s(st + STG_A_HI, aHiB + (size_t)i*TILE_BYTES, mb);
            bulk_g2s(st + STG_A_LO, aLoB + (size_t)i*TILE_BYTES, mb);
            bulk_g2s(st + STG_B_HI, bHiB + (size_t)i*TILE_BYTES, mb);
            bulk_g2s(st + STG_B_LO, bLoB + (size_t)i*TILE_BYTES, mb);
        }

        const uint32_t stage = sb + 1024 + stage_c*STAGE_BYTES;
        #pragma unroll
        for (int kk = 0; kk < 2; kk++) {
            const uint32_t kbx = ((uint32_t)kk*32 + laneC) ^ xorM;

            uint32_t bhiF[4][2], bloF[4][2];
            #pragma unroll
            for (int g = 0; g < 2; g++) {
                uint32_t off = bBase + (uint32_t)g*1024 + kbx;
                uint32_t t0, t1, t2, t3;
                ldsm_x4(t0, t1, t2, t3, stage + STG_B_HI + off);
                bhiF[2*g][0] = t0; bhiF[2*g][1] = t2; bhiF[2*g+1][0] = t1; bhiF[2*g+1][1] = t3;
                ldsm_x4(t0, t1, t2, t3, stage + STG_B_LO + off);
                bloF[2*g][0] = t0; bloF[2*g][1] = t2; bloF[2*g+1][0] = t1; bloF[2*g+1][1] = t3;
            }
            uint32_t ahiF[2][4], aloF[2][4];
            {
                uint32_t off = aBase + kbx;
                ldsm_x4(ahiF[0][0], ahiF[0][1], ahiF[0][2], ahiF[0][3], stage + STG_A_HI + off);
                ldsm_x4(aloF[0][0], aloF[0][1], aloF[0][2], aloF[0][3], stage + STG_A_LO + off);
            }
            #pragma unroll
            for (int mf = 0; mf < 4; mf++) {
                const int cur = mf & 1, nxt = cur ^ 1;
                if (mf < 3) {
                    uint32_t off = aBase + (uint32_t)(mf+1)*1024 + kbx;
                    ldsm_x4(ahiF[nxt][0], ahiF[nxt][1], ahiF[nxt][2], ahiF[nxt][3],
                            stage + STG_A_HI + off);
                    ldsm_x4(aloF[nxt][0], aloF[nxt][1], aloF[nxt][2], aloF[nxt][3],
                            stage + STG_A_LO + off);
                }
                if (kk == 1 && mf == 3 && lane == 0)
                    mbar_arrive(sb + 24 + stage_c*8);
                #pragma unroll
                for (int nf = 0; nf < 4; nf++)
                    mma16816(acc[mf][nf], ahiF[cur], bhiF[nf]);
                #pragma unroll
                for (int nf = 0; nf < 4; nf++)
                    mma16816(acc[mf][nf], ahiF[cur], bloF[nf]);
                #pragma unroll
                for (int nf = 0; nf < 4; nf++)
                    mma16816(acc[mf][nf], aloF[cur], bhiF[nf]);
            }
        }
        stage_c++; if (stage_c >= NSTAGE) stage_c -= NSTAGE;
    }

    const int g = lane >> 2, q = lane & 3;

    if (!isProj) {
        float rs[8];
        #pragma unroll
        for (int i = 0; i < 8; i++) rs[i] = 0.0f;
        #pragma unroll
        for (int mf = 0; mf < 4; mf++) {
            #pragma unroll
            for (int nf = 0; nf < 4; nf++) {
                const int col = ncol0 + warp_n*32 + nf*8 + q*2;
                const float r0 = __ldg(&rkb[col]);
                const float r1 = __ldg(&rkb[col+1]);
                acc[mf][nf][0] = exp2f(fmaf(acc[mf][nf][0], EXP2_SCALE, r0));
                acc[mf][nf][1] = exp2f(fmaf(acc[mf][nf][1], EXP2_SCALE, r1));
                acc[mf][nf][2] = exp2f(fmaf(acc[mf][nf][2], EXP2_SCALE, r0));
                acc[mf][nf][3] = exp2f(fmaf(acc[mf][nf][3], EXP2_SCALE, r1));
                rs[mf*2 + 0] += acc[mf][nf][0] + acc[mf][nf][1];
                rs[mf*2 + 1] += acc[mf][nf][2] + acc[mf][nf][3];
            }
        }
        #pragma unroll
        for (int i = 0; i < 8; i++) {
            rs[i] += __shfl_xor_sync(0xffffffffu, rs[i], 1);
            rs[i] += __shfl_xor_sync(0xffffffffu, rs[i], 2);
        }
        if (q == 0) {
            #pragma unroll
            for (int i = 0; i < 8; i++)
                s_rowsum[warp_m*64 + (i>>1)*16 + (i&1)*8 + g][warp_n] = rs[i];
        }
        __syncthreads();
        if (tid < 128) {
            float s = s_rowsum[tid][0] + s_rowsum[tid][1] + s_rowsum[tid][2] + s_rowsum[tid][3];
            psum[((size_t)arow0 + tid)*NT_ + sbx] = s;
        }

        __threadfence();
        __syncthreads();
        if (tid == 0) {
            atomicAdd(&scnt[atile], 1u);
            spin_ge(scnt + atile, (unsigned)NT_);
        }
        __syncthreads();
        __threadfence();
        if (tid < 128) {
            const float* pr = &psum[((size_t)arow0 + tid) * NT_];
            float s = 0.0f;
            #pragma unroll
            for (int t = 0; t < NT_; t++) s += pr[t];
            s_inv[tid] = 1.0f / s;
        }
        __syncthreads();

        #pragma unroll
        for (int mf = 0; mf < 4; mf++) {
            const int r0 = warp_m*64 + mf*16 + g;
            const float iv0 = s_inv[r0];
            const float iv1 = s_inv[r0 + 8];
            const size_t grow = (size_t)arow0 + r0;
            #pragma unroll
            for (int nf = 0; nf < 4; nf++) {
                const int col = ncol0 + warp_n*32 + nf*8 + q*2;
                *reinterpret_cast<float2*>(&outF[grow*S_ + col]) =
                    make_float2(acc[mf][nf][0]*iv0, acc[mf][nf][1]*iv0);
                *reinterpret_cast<float2*>(&outF[(grow+8)*S_ + col]) =
                    make_float2(acc[mf][nf][2]*iv1, acc[mf][nf][3]*iv1);
            }
        }

        if (tid == 0) {
            unsigned int old = atomicInc(&srd[atile], 15u);
            if (old == 15u) scnt[atile] = 0u;
        }
    } else {
        char* oh = (char*)uhi + (size_t)atile * 16 * TILE_BYTES;
        char* ol = (char*)ulo + (size_t)atile * 16 * TILE_BYTES;
        #pragma unroll
        for (int mf = 0; mf < 4; mf++) {
            const int r0 = warp_m*64 + mf*16 + g;
            #pragma unroll
            for (int nf = 0; nf < 4; nf++) {
                const int col = ncol0 + warp_n*32 + nf*8 + q*2;
                float v0 = acc[mf][nf][0];
                float v1 = acc[mf][nf][1];
                float v2v = acc[mf][nf][2];
                float v3 = acc[mf][nf][3];
                __nv_bfloat162 h01, l01, h23, l23;
                h01.x = __float2bfloat16(v0); h01.y = __float2bfloat16(v1);
                l01.x = __float2bfloat16(v0 - __bfloat162float(h01.x));
                l01.y = __float2bfloat16(v1 - __bfloat162float(h01.y));
                h23.x = __float2bfloat16(v2v); h23.y = __float2bfloat16(v3);
                l23.x = __float2bfloat16(v2v - __bfloat162float(h23.x));
                l23.y = __float2bfloat16(v3 - __bfloat162float(h23.y));
                uint32_t o0 = blk_off(r0,     col);
                uint32_t o1 = blk_off(r0 + 8, col);
                *reinterpret_cast<__nv_bfloat162*>(oh + o0) = h01;
                *reinterpret_cast<__nv_bfloat162*>(ol + o0) = l01;
                *reinterpret_cast<__nv_bfloat162*>(oh + o1) = h23;
                *reinterpret_cast<__nv_bfloat162*>(ol + o1) = l23;
            }
        }
        __threadfence();
        __syncthreads();
        if (tid == 0) atomicAdd(&uflag[atile], 1u);
    }
}

// ---------------- launcher ----------------
extern "C" void kernel_launch(void* const* d_in, const int* in_sizes, int n_in,
                              void* d_out, int out_size)
{
    const float* x  = (const float*)d_in[0];
    const float* Wq = (const float*)d_in[1];
    const float* bq = (const float*)d_in[2];
    const float* Wk = (const float*)d_in[3];
    float* out = (float*)d_out;

    __nv_bfloat16 *xhi, *xlo, *m2hi, *m2lo, *uhi, *ulo;
    float *v2p, *rkp, *pptr;
    unsigned int *v2fp, *v2rdp, *uflagp, *urdp, *scntp, *srdp;
    cudaGetSymbolAddress((void**)&xhi,  g_xhi);
    cudaGetSymbolAddress((void**)&xlo,  g_xlo);
    cudaGetSymbolAddress((void**)&m2hi, g_m2hi);
    cudaGetSymbolAddress((void**)&m2lo, g_m2lo);
    cudaGetSymbolAddress((void**)&uhi,  g_uhi);
    cudaGetSymbolAddress((void**)&ulo,  g_ulo);
    cudaGetSymbolAddress((void**)&v2p,  g_v2);
    cudaGetSymbolAddress((void**)&rkp,  g_rk);
    cudaGetSymbolAddress((void**)&pptr, g_psum);
    cudaGetSymbolAddress((void**)&v2fp,  g_v2flag);
    cudaGetSymbolAddress((void**)&v2rdp, g_v2rd);
    cudaGetSymbolAddress((void**)&uflagp, g_uflag);
    cudaGetSymbolAddress((void**)&urdp,   g_u_rd);
    cudaGetSymbolAddress((void**)&scntp,  g_scnt);
    cudaGetSymbolAddress((void**)&srdp,   g_srd);

    cudaFuncSetAttribute(fused_gemm_kernel, cudaFuncAttributeMaxDynamicSharedMemorySize, SMEM_DYN);
    cudaFuncSetAttribute(prep_kernel, cudaFuncAttributeMaxDynamicSharedMemorySize, PREP_SMEM);

    // 1) ONE prep launch: v2 | m2t | split run co-resident
    prep_kernel<<<PREP_GRID, 256, PREP_SMEM>>>(
        x, Wk, Wq, bq, v2p, rkp, xhi, xlo, m2hi, m2lo, v2fp, v2rdp);

    // 2) fused proj + scores + softmax (R13)
    fused_gemm_kernel<<<N_PROJ_CTAS + S_/BN * S_/BM * B_, 256, SMEM_DYN>>>(
        xhi, xlo, m2hi, m2lo, uhi, ulo, rkp, out, pptr,
        uflagp, urdp, scntp, srdp);
}

// round 16
// speedup vs baseline: 1.0506x; 1.0330x over previous
#include <cuda_runtime.h>
#include <cuda_bf16.h>
#include <cstdint>
#include <math.h>

#define B_  8
#define S_  2048
#define D_  512
#define NT_ 16          // psum slots per row (S_/128 column tiles)

// ---- GEMM tile config ----
#define BM 128
#define BN 128
#define KC 32
#define NCHUNK (D_/KC)  // 16
#define NSTAGE 3

#define TILE_BYTES 8192

#define STG_A_HI 0
#define STG_A_LO 8192
#define STG_B_HI 16384
#define STG_B_LO 24576
#define STAGE_BYTES 32768
#define SMEM_DYN (2048 + NSTAGE*STAGE_BYTES)   // 100352

#define N_PROJ_CTAS 512      // proj role: ids [0, 512)
#define N_UTILES    128

// (1/sqrt(512)) * log2(e)
#define EXP2_SCALE 0.06376070918938434f

// ---------------- scratch ----------------
__device__ __nv_bfloat16 g_xhi[B_*S_*D_];
__device__ __nv_bfloat16 g_xlo[B_*S_*D_];
__device__ __nv_bfloat16 g_m2hi[D_*D_];
__device__ __nv_bfloat16 g_m2lo[D_*D_];
__device__ __nv_bfloat16 g_uhi[B_*S_*D_];
__device__ __nv_bfloat16 g_ulo[B_*S_*D_];
__device__ float         g_v2[D_];
__device__ float         g_rk[B_*S_];
__device__ float         g_psum[B_*S_*NT_];
__device__ unsigned int  g_uflag[N_UTILES];   // proj arrivals (4 per tile)
__device__ unsigned int  g_u_rd[N_UTILES];    // readers wrap 15
__device__ unsigned int  g_scnt[N_UTILES];    // scores psum arrivals (16)
__device__ unsigned int  g_srd[N_UTILES];     // readers wrap 15

// ---------------- helpers ----------------
__device__ __forceinline__ uint32_t smem_u32(const void* p) {
    uint32_t a;
    asm("{ .reg .u64 t; cvta.to.shared.u64 t, %1; cvt.u32.u64 %0, t; }" : "=r"(a) : "l"(p));
    return a;
}
__device__ __forceinline__ uint32_t swz64(uint32_t off) {
    return off ^ ((off >> 3) & 0x30);
}
__device__ __forceinline__ void mbar_init(uint32_t m, uint32_t cnt) {
    asm volatile("mbarrier.init.shared.b64 [%0], %1;" :: "r"(m), "r"(cnt) : "memory");
}
__device__ __forceinline__ void mbar_wait(uint32_t m, uint32_t parity) {
    asm volatile(
        "{\n\t.reg .pred P;\n\t"
        "W_%=:\n\t"
        "mbarrier.try_wait.parity.shared::cta.b64 P, [%0], %1, 10000000;\n\t"
        "@P bra.uni D_%=;\n\t"
        "bra.uni W_%=;\n\t"
        "D_%=:\n\t}"
        :: "r"(m), "r"(parity) : "memory");
}
__device__ __forceinline__ void mbar_arrive(uint32_t m) {
    asm volatile("mbarrier.arrive.shared.b64 _, [%0];" :: "r"(m) : "memory");
}
__device__ __forceinline__ void mbar_expect_tx(uint32_t m, uint32_t bytes) {
    asm volatile("mbarrier.arrive.expect_tx.shared.b64 _, [%0], %1;"
                 :: "r"(m), "r"(bytes) : "memory");
}
__device__ __forceinline__ void bulk_g2s(uint32_t dst, const void* src, uint32_t mbar) {
    asm volatile(
        "cp.async.bulk.shared::cluster.global.mbarrier::complete_tx::bytes [%0], [%1], %2, [%3];"
        :: "r"(dst), "l"(src), "r"((uint32_t)TILE_BYTES), "r"(mbar) : "memory");
}
__device__ __forceinline__ void ldsm_x4(uint32_t& r0, uint32_t& r1, uint32_t& r2, uint32_t& r3,
                                        uint32_t addr) {
    asm volatile("ldmatrix.sync.aligned.m8n8.x4.shared.b16 {%0,%1,%2,%3}, [%4];"
                 : "=r"(r0), "=r"(r1), "=r"(r2), "=r"(r3) : "r"(addr));
}
__device__ __forceinline__ void mma16816(float* c, const uint32_t* a, const uint32_t* b) {
    asm volatile(
        "mma.sync.aligned.m16n8k16.row.col.f32.bf16.bf16.f32 "
        "{%0,%1,%2,%3}, {%4,%5,%6,%7}, {%8,%9}, {%0,%1,%2,%3};"
        : "+f"(c[0]), "+f"(c[1]), "+f"(c[2]), "+f"(c[3])
        : "r"(a[0]), "r"(a[1]), "r"(a[2]), "r"(a[3]), "r"(b[0]), "r"(b[1]));
}
__device__ __forceinline__ uint32_t blk_off(int r128, int col) {
    return (uint32_t)(col >> 5) * TILE_BYTES + swz64((uint32_t)(r128*64 + (col & 31)*2));
}
__device__ __forceinline__ void spin_ge(volatile unsigned int* f, unsigned int tgt) {
    while (*f < tgt) __nanosleep(64);
}

// ---------------- prep kernels (R13 structure) ----------------
__global__ __launch_bounds__(256)
void v2_kernel(const float* __restrict__ Wk, const float* __restrict__ bq,
               float* __restrict__ v2)
{
    const int lane = threadIdx.x & 31;
    const int wrow = blockIdx.x * 8 + (threadIdx.x >> 5);
    float s = 0.0f;
    #pragma unroll
    for (int i = 0; i < 16; i++) {
        int d = i*32 + lane;
        s += Wk[(size_t)wrow*D_ + d] * bq[d];
    }
    #pragma unroll
    for (int o = 16; o > 0; o >>= 1) s += __shfl_xor_sync(0xffffffffu, s, o);
    if (lane == 0) v2[wrow] = s;
}

// warp-per-row split: fully coalesced reads, 64B-segment swizzled writes
__global__ __launch_bounds__(256)
void split_x_rk_kernel(const float* __restrict__ in, const float* __restrict__ v2,
                       __nv_bfloat16* __restrict__ hi, __nv_bfloat16* __restrict__ lo,
                       float* __restrict__ rk)
{
    const int lane = threadIdx.x & 31;
    const int row  = blockIdx.x * 8 + (threadIdx.x >> 5);
    const float4* src = reinterpret_cast<const float4*>(in) + (size_t)row * (D_/4);
    const float4* w4  = reinterpret_cast<const float4*>(v2);
    const size_t tbase = ((size_t)(row >> 7) * 16) * TILE_BYTES;
    const int r128 = row & 127;
    float local = 0.0f;
    #pragma unroll
    for (int j = 0; j < 4; j++) {
        const int c4 = j*32 + lane;            // float4 index within row (0..127)
        float4 v = src[c4];
        float4 w = w4[c4];
        local += v.x*w.x + v.y*w.y + v.z*w.z + v.w*w.w;
        __nv_bfloat16 h[4], l[4];
        h[0] = __float2bfloat16(v.x); l[0] = __float2bfloat16(v.x - __bfloat162float(h[0]));
        h[1] = __float2bfloat16(v.y); l[1] = __float2bfloat16(v.y - __bfloat162float(h[1]));
        h[2] = __float2bfloat16(v.z); l[2] = __float2bfloat16(v.z - __bfloat162float(h[2]));
        h[3] = __float2bfloat16(v.w); l[3] = __float2bfloat16(v.w - __bfloat162float(h[3]));
        const uint32_t off = blk_off(r128, c4*4);   // 8B-aligned inside swizzle unit
        *reinterpret_cast<uint2*>((char*)hi + tbase + off) = *reinterpret_cast<uint2*>(h);
        *reinterpret_cast<uint2*>((char*)lo + tbase + off) = *reinterpret_cast<uint2*>(l);
    }
    #pragma unroll
    for (int o = 16; o > 0; o >>= 1) local += __shfl_xor_sync(0xffffffffu, local, o);
    if (lane == 0) rk[row] = local * EXP2_SCALE;
}

__global__ __launch_bounds__(256)
void m2t_kernel(const float* __restrict__ Wk, const float* __restrict__ Wq,
                __nv_bfloat16* __restrict__ m2hi, __nv_bfloat16* __restrict__ m2lo)
{
    __shared__ float sk[32][33];
    __shared__ float sq[32][33];
    const int tid = threadIdx.x;
    const int g0 = blockIdx.y * 32, f0 = blockIdx.x * 32;
    const int ty = tid >> 4, tx = tid & 15;

    float acc[2][2] = {{0.f,0.f},{0.f,0.f}};
    for (int d0 = 0; d0 < D_; d0 += 32) {
        #pragma unroll
        for (int p = 0; p < 4; p++) {
            int e = p*256 + tid;
            int r = e >> 5, c = e & 31;
            sk[r][c] = Wk[(size_t)(g0+r)*D_ + d0 + c];
            sq[r][c] = Wq[(size_t)(f0+r)*D_ + d0 + c];
        }
        __syncthreads();
        #pragma unroll
        for (int d = 0; d < 32; d++) {
            float k0v = sk[2*ty][d],   k1v = sk[2*ty+1][d];
            float q0v = sq[2*tx][d],   q1v = sq[2*tx+1][d];
            acc[0][0] = fmaf(k0v, q0v, acc[0][0]);
            acc[0][1] = fmaf(k0v, q1v, acc[0][1]);
            acc[1][0] = fmaf(k1v, q0v, acc[1][0]);
            acc[1][1] = fmaf(k1v, q1v, acc[1][1]);
        }
        __syncthreads();
    }
    #pragma unroll
    for (int i = 0; i < 2; i++)
        #pragma unroll
        for (int j = 0; j < 2; j++) {
            float v = acc[i][j];
            __nv_bfloat16 h = __float2bfloat16(v);
            __nv_bfloat16 l = __float2bfloat16(v - __bfloat162float(h));
            int g = g0 + 2*ty + i;
            int f = f0 + 2*tx + j;
            size_t tbase = ((size_t)(g >> 7) * 16) * TILE_BYTES;
            uint32_t off = blk_off(g & 127, f);
            *reinterpret_cast<__nv_bfloat16*>((char*)m2hi + tbase + off) = h;
            *reinterpret_cast<__nv_bfloat16*>((char*)m2lo + tbase + off) = l;
        }
}

// ---------------- fused proj+scores+softmax NT GEMM (R13, unchanged) --------
__global__ __launch_bounds__(256, 2)
void fused_gemm_kernel(const __nv_bfloat16* __restrict__ xhi,
                       const __nv_bfloat16* __restrict__ xlo,
                       const __nv_bfloat16* __restrict__ m2hi,
                       const __nv_bfloat16* __restrict__ m2lo,
                       __nv_bfloat16* __restrict__ uhi,
                       __nv_bfloat16* __restrict__ ulo,
                       const float* __restrict__ rk,
                       float* __restrict__ outF,
                       float* __restrict__ psum,
                       unsigned int* uflag,
                       unsigned int* rcnt,
                       unsigned int* scnt,
                       unsigned int* srd)
{
    extern __shared__ char smem_raw[];
    const uint32_t sb = (smem_u32(smem_raw) + 1023u) & ~1023u;
    __shared__ float s_rowsum[128][4];
    __shared__ float s_inv[128];

    const int id     = blockIdx.x;
    const bool isProj = (id < N_PROJ_CTAS);
    const int tid    = threadIdx.x;
    const int lane   = tid & 31;
    const int wid    = tid >> 5;
    const int warp_m = wid & 1;
    const int warp_n = wid >> 1;

    int atile, btile, arow0, ncol0, sbx = 0, sbz = 0;
    const __nv_bfloat16 *aHiT, *aLoT, *bHiT, *bLoT;
    if (isProj) {
        const int bx = id & 3, by = id >> 2;
        atile = by; btile = bx;
        arow0 = by * BM; ncol0 = bx * BN;
        aHiT = xhi;  aLoT = xlo;  bHiT = m2hi; bLoT = m2lo;
    } else {
        const int sid = id - N_PROJ_CTAS;
        sbx = sid & 15;
        const int sby = (sid >> 4) & 15;
        sbz = sid >> 8;
        atile = sbz * 16 + sby;
        btile = sbz * 16 + sbx;
        arow0 = atile * BM; ncol0 = sbx * BN;
        aHiT = uhi;  aLoT = ulo;  bHiT = xhi;  bLoT = xlo;
    }
    const char* aHiB = (const char*)aHiT + (size_t)atile * 16 * TILE_BYTES;
    const char* aLoB = (const char*)aLoT + (size_t)atile * 16 * TILE_BYTES;
    const char* bHiB = (const char*)bHiT + (size_t)btile * 16 * TILE_BYTES;
    const char* bLoB = (const char*)bLoT + (size_t)btile * 16 * TILE_BYTES;
    const float* rkb = rk + (size_t)sbz * S_;

    if (tid == 0) {
        #pragma unroll
        for (int s = 0; s < NSTAGE; s++) {
            mbar_init(sb + s*8, 1);
            mbar_init(sb + 24 + s*8, 8);
        }
    }
    __syncthreads();

    if (tid == 0) {
        if (!isProj) {
            spin_ge(uflag + atile, 4u);
            __threadfence();
            unsigned int old = atomicInc(&rcnt[atile], 15u);
            if (old == 15u) uflag[atile] = 0u;
        }
        #pragma unroll
        for (int i = 0; i < 2; i++) {
            uint32_t st = sb + 1024 + i*STAGE_BYTES;
            uint32_t mb = sb + i*8;
            mbar_expect_tx(mb, STAGE_BYTES);
            bulk_g2s(st + STG_A_HI, aHiB + (size_t)i*TILE_BYTES, mb);
            bulk_g2s(st + STG_A_LO, aLoB + (size_t)i*TILE_BYTES, mb);
            bulk_g2s(st + STG_B_HI, bHiB + (size_t)i*TILE_BYTES, mb);
            bulk_g2s(st + STG_B_LO, bLoB + (size_t)i*TILE_BYTES, mb);
        }
    }

    const int laneR = lane & 15;
    const uint32_t laneC = (uint32_t)(lane >> 4) * 16;
    const uint32_t xorM  = (uint32_t)(laneR & 6) << 3;
    const uint32_t aBase = (uint32_t)(warp_m*64 + laneR) * 64;
    const uint32_t bBase = (uint32_t)(warp_n*32 + laneR) * 64;

    float acc[4][4][4];
    #pragma unroll
    for (int i = 0; i < 4; i++)
        #pragma unroll
        for (int j = 0; j < 4; j++)
            #pragma unroll
            for (int k = 0; k < 4; k++) acc[i][j][k] = 0.0f;

    int stage_c = 0;
    for (int c = 0; c < NCHUNK; c++) {
        mbar_wait(sb + stage_c*8, (c/NSTAGE) & 1);

        if (tid == 0 && c + 2 < NCHUNK) {
            const int i = c + 2;
            int si = stage_c + 2; if (si >= NSTAGE) si -= NSTAGE;
            if (i >= NSTAGE)
                mbar_wait(sb + 24 + si*8, ((i/NSTAGE) - 1) & 1);
            uint32_t st = sb + 1024 + si*STAGE_BYTES;
            uint32_t mb = sb + si*8;
            mbar_expect_tx(mb, STAGE_BYTES);
            bulk_g2s(st + STG_A_HI, aHiB + (size_t)i*TILE_BYTES, mb);
            bulk_g2s(st + STG_A_LO, aLoB + (size_t)i*TILE_BYTES, mb);
            bulk_g2s(st + STG_B_HI, bHiB + (size_t)i*TILE_BYTES, mb);
            bulk_g2s(st + STG_B_LO, bLoB + (size_t)i*TILE_BYTES, mb);
        }

        const uint32_t stage = sb + 1024 + stage_c*STAGE_BYTES;
        #pragma unroll
        for (int kk = 0; kk < 2; kk++) {
            const uint32_t kbx = ((uint32_t)kk*32 + laneC) ^ xorM;

            uint32_t bhiF[4][2], bloF[4][2];
            #pragma unroll
            for (int g = 0; g < 2; g++) {
                uint32_t off = bBase + (uint32_t)g*1024 + kbx;
                uint32_t t0, t1, t2, t3;
                ldsm_x4(t0, t1, t2, t3, stage + STG_B_HI + off);
                bhiF[2*g][0] = t0; bhiF[2*g][1] = t2; bhiF[2*g+1][0] = t1; bhiF[2*g+1][1] = t3;
                ldsm_x4(t0, t1, t2, t3, stage + STG_B_LO + off);
                bloF[2*g][0] = t0; bloF[2*g][1] = t2; bloF[2*g+1][0] = t1; bloF[2*g+1][1] = t3;
            }
            uint32_t ahiF[2][4], aloF[2][4];
            {
                uint32_t off = aBase + kbx;
                ldsm_x4(ahiF[0][0], ahiF[0][1], ahiF[0][2], ahiF[0][3], stage + STG_A_HI + off);
                ldsm_x4(aloF[0][0], aloF[0][1], aloF[0][2], aloF[0][3], stage + STG_A_LO + off);
            }
            #pragma unroll
            for (int mf = 0; mf < 4; mf++) {
                const int cur = mf & 1, nxt = cur ^ 1;
                if (mf < 3) {
                    uint32_t off = aBase + (uint32_t)(mf+1)*1024 + kbx;
                    ldsm_x4(ahiF[nxt][0], ahiF[nxt][1], ahiF[nxt][2], ahiF[nxt][3],
                            stage + STG_A_HI + off);
                    ldsm_x4(aloF[nxt][0], aloF[nxt][1], aloF[nxt][2], aloF[nxt][3],
                            stage + STG_A_LO + off);
                }
                if (kk == 1 && mf == 3 && lane == 0)
                    mbar_arrive(sb + 24 + stage_c*8);
                #pragma unroll
                for (int nf = 0; nf < 4; nf++)
                    mma16816(acc[mf][nf], ahiF[cur], bhiF[nf]);
                #pragma unroll
                for (int nf = 0; nf < 4; nf++)
                    mma16816(acc[mf][nf], ahiF[cur], bloF[nf]);
                #pragma unroll
                for (int nf = 0; nf < 4; nf++)
                    mma16816(acc[mf][nf], aloF[cur], bhiF[nf]);
            }
        }
        stage_c++; if (stage_c >= NSTAGE) stage_c -= NSTAGE;
    }

    const int g = lane >> 2, q = lane & 3;

    if (!isProj) {
        float rs[8];
        #pragma unroll
        for (int i = 0; i < 8; i++) rs[i] = 0.0f;
        #pragma unroll
        for (int mf = 0; mf < 4; mf++) {
            #pragma unroll
            for (int nf = 0; nf < 4; nf++) {
                const int col = ncol0 + warp_n*32 + nf*8 + q*2;
                const float r0 = __ldg(&rkb[col]);
                const float r1 = __ldg(&rkb[col+1]);
                acc[mf][nf][0] = exp2f(fmaf(acc[mf][nf][0], EXP2_SCALE, r0));
                acc[mf][nf][1] = exp2f(fmaf(acc[mf][nf][1], EXP2_SCALE, r1));
                acc[mf][nf][2] = exp2f(fmaf(acc[mf][nf][2], EXP2_SCALE, r0));
                acc[mf][nf][3] = exp2f(fmaf(acc[mf][nf][3], EXP2_SCALE, r1));
                rs[mf*2 + 0] += acc[mf][nf][0] + acc[mf][nf][1];
                rs[mf*2 + 1] += acc[mf][nf][2] + acc[mf][nf][3];
            }
        }
        #pragma unroll
        for (int i = 0; i < 8; i++) {
            rs[i] += __shfl_xor_sync(0xffffffffu, rs[i], 1);
            rs[i] += __shfl_xor_sync(0xffffffffu, rs[i], 2);
        }
        if (q == 0) {
            #pragma unroll
            for (int i = 0; i < 8; i++)
                s_rowsum[warp_m*64 + (i>>1)*16 + (i&1)*8 + g][warp_n] = rs[i];
        }
        __syncthreads();
        if (tid < 128) {
            float s = s_rowsum[tid][0] + s_rowsum[tid][1] + s_rowsum[tid][2] + s_rowsum[tid][3];
            psum[((size_t)arow0 + tid)*NT_ + sbx] = s;
        }

        __threadfence();
        __syncthreads();
        if (tid == 0) {
            atomicAdd(&scnt[atile], 1u);
            spin_ge(scnt + atile, (unsigned)NT_);
        }
        __syncthreads();
        __threadfence();
        if (tid < 128) {
            const float* pr = &psum[((size_t)arow0 + tid) * NT_];
            float s = 0.0f;
            #pragma unroll
            for (int t = 0; t < NT_; t++) s += pr[t];
            s_inv[tid] = 1.0f / s;
        }
        __syncthreads();

        #pragma unroll
        for (int mf = 0; mf < 4; mf++) {
            const int r0 = warp_m*64 + mf*16 + g;
            const float iv0 = s_inv[r0];
            const float iv1 = s_inv[r0 + 8];
            const size_t grow = (size_t)arow0 + r0;
            #pragma unroll
            for (int nf = 0; nf < 4; nf++) {
                const int col = ncol0 + warp_n*32 + nf*8 + q*2;
                *reinterpret_cast<float2*>(&outF[grow*S_ + col]) =
                    make_float2(acc[mf][nf][0]*iv0, acc[mf][nf][1]*iv0);
                *reinterpret_cast<float2*>(&outF[(grow+8)*S_ + col]) =
                    make_float2(acc[mf][nf][2]*iv1, acc[mf][nf][3]*iv1);
            }
        }

        if (tid == 0) {
            unsigned int old = atomicInc(&srd[atile], 15u);
            if (old == 15u) scnt[atile] = 0u;
        }
    } else {
        char* oh = (char*)uhi + (size_t)atile * 16 * TILE_BYTES;
        char* ol = (char*)ulo + (size_t)atile * 16 * TILE_BYTES;
        #pragma unroll
        for (int mf = 0; mf < 4; mf++) {
            const int r0 = warp_m*64 + mf*16 + g;
            #pragma unroll
            for (int nf = 0; nf < 4; nf++) {
                const int col = ncol0 + warp_n*32 + nf*8 + q*2;
                float v0 = acc[mf][nf][0];
                float v1 = acc[mf][nf][1];
                float v2v = acc[mf][nf][2];
                float v3 = acc[mf][nf][3];
                __nv_bfloat162 h01, l01, h23, l23;
                h01.x = __float2bfloat16(v0); h01.y = __float2bfloat16(v1);
                l01.x = __float2bfloat16(v0 - __bfloat162float(h01.x));
                l01.y = __float2bfloat16(v1 - __bfloat162float(h01.y));
                h23.x = __float2bfloat16(v2v); h23.y = __float2bfloat16(v3);
                l23.x = __float2bfloat16(v2v - __bfloat162float(h23.x));
                l23.y = __float2bfloat16(v3 - __bfloat162float(h23.y));
                uint32_t o0 = blk_off(r0,     col);
                uint32_t o1 = blk_off(r0 + 8, col);
                *reinterpret_cast<__nv_bfloat162*>(oh + o0) = h01;
                *reinterpret_cast<__nv_bfloat162*>(ol + o0) = l01;
                *reinterpret_cast<__nv_bfloat162*>(oh + o1) = h23;
                *reinterpret_cast<__nv_bfloat162*>(ol + o1) = l23;
            }
        }
        __threadfence();
        __syncthreads();
        if (tid == 0) atomicAdd(&uflag[atile], 1u);
    }
}

// ---------------- launcher ----------------
extern "C" void kernel_launch(void* const* d_in, const int* in_sizes, int n_in,
                              void* d_out, int out_size)
{
    const float* x  = (const float*)d_in[0];
    const float* Wq = (const float*)d_in[1];
    const float* bq = (const float*)d_in[2];
    const float* Wk = (const float*)d_in[3];
    float* out = (float*)d_out;

    __nv_bfloat16 *xhi, *xlo, *m2hi, *m2lo, *uhi, *ulo;
    float *v2p, *rkp, *pptr;
    unsigned int *uflagp, *urdp, *scntp, *srdp;
    cudaGetSymbolAddress((void**)&xhi,  g_xhi);
    cudaGetSymbolAddress((void**)&xlo,  g_xlo);
    cudaGetSymbolAddress((void**)&m2hi, g_m2hi);
    cudaGetSymbolAddress((void**)&m2lo, g_m2lo);
    cudaGetSymbolAddress((void**)&uhi,  g_uhi);
    cudaGetSymbolAddress((void**)&ulo,  g_ulo);
    cudaGetSymbolAddress((void**)&v2p,  g_v2);
    cudaGetSymbolAddress((void**)&rkp,  g_rk);
    cudaGetSymbolAddress((void**)&pptr, g_psum);
    cudaGetSymbolAddress((void**)&uflagp, g_uflag);
    cudaGetSymbolAddress((void**)&urdp,   g_u_rd);
    cudaGetSymbolAddress((void**)&scntp,  g_scnt);
    cudaGetSymbolAddress((void**)&srdp,   g_srd);

    cudaFuncSetAttribute(fused_gemm_kernel, cudaFuncAttributeMaxDynamicSharedMemorySize, SMEM_DYN);

    // 1) preps (R13 structure; split rewritten warp-per-row)
    v2_kernel<<<D_/8, 256>>>(Wk, bq, v2p);
    split_x_rk_kernel<<<B_*S_/8, 256>>>(x, v2p, xhi, xlo, rkp);
    dim3 mg(D_/32, D_/32);
    m2t_kernel<<<mg, 256>>>(Wk, Wq, m2hi, m2lo);

    // 2) fused proj + scores + softmax (single output write)
    fused_gemm_kernel<<<N_PROJ_CTAS + S_/BN * S_/BM * B_, 256, SMEM_DYN>>>(
        xhi, xlo, m2hi, m2lo, uhi, ulo, rkp, out, pptr,
        uflagp, urdp, scntp, srdp);
}

// round 17
// speedup vs baseline: 1.0640x; 1.0128x over previous
#include <cuda_runtime.h>
#include <cuda_bf16.h>
#include <cstdint>
#include <math.h>

#define B_  8
#define S_  2048
#define D_  512
#define NT_ 16          // psum slots per row (S_/128 column tiles)

// ---- GEMM tile config ----
#define BM 128
#define BN 128
#define KC 32
#define NCHUNK (D_/KC)  // 16
#define NSTAGE 3

// combined hi|lo block per (tile, chunk): 16 KB (hi 8K, lo 8K), swizzled
#define CHUNK_BYTES 16384
#define TILE_STRIDE ((size_t)16 * CHUNK_BYTES)    // per 128-row tile

#define STG_A 0          // A hi at 0, A lo at 8192
#define STG_B 16384      // B hi at 16384, B lo at 24576
#define STAGE_BYTES 32768
#define SMEM_DYN (2048 + NSTAGE*STAGE_BYTES)   // 100352

#define N_PROJ_CTAS 512
#define N_UTILES    128

// (1/sqrt(512)) * log2(e)
#define EXP2_SCALE 0.06376070918938434f

// ---------------- scratch (combined hi|lo blocked layouts) ----------------
__device__ __nv_bfloat16 g_x [B_*S_*D_*2];
__device__ __nv_bfloat16 g_m2[D_*D_*2];
__device__ __nv_bfloat16 g_u [B_*S_*D_*2];
__device__ float         g_v2[D_];
__device__ float         g_rk[B_*S_];
__device__ float         g_psum[B_*S_*NT_];
__device__ unsigned int  g_uflag[N_UTILES];   // proj arrivals (4 per tile)
__device__ unsigned int  g_u_rd[N_UTILES];    // readers wrap 15
__device__ unsigned int  g_scnt[N_UTILES];    // scores psum arrivals (16)
__device__ unsigned int  g_srd[N_UTILES];     // readers wrap 15

// ---------------- helpers ----------------
__device__ __forceinline__ uint32_t smem_u32(const void* p) {
    uint32_t a;
    asm("{ .reg .u64 t; cvta.to.shared.u64 t, %1; cvt.u32.u64 %0, t; }" : "=r"(a) : "l"(p));
    return a;
}
__device__ __forceinline__ uint32_t swz64(uint32_t off) {
    return off ^ ((off >> 3) & 0x30);
}
__device__ __forceinline__ void mbar_init(uint32_t m, uint32_t cnt) {
    asm volatile("mbarrier.init.shared.b64 [%0], %1;" :: "r"(m), "r"(cnt) : "memory");
}
__device__ __forceinline__ void mbar_wait(uint32_t m, uint32_t parity) {
    asm volatile(
        "{\n\t.reg .pred P;\n\t"
        "W_%=:\n\t"
        "mbarrier.try_wait.parity.shared::cta.b64 P, [%0], %1, 10000000;\n\t"
        "@P bra.uni D_%=;\n\t"
        "bra.uni W_%=;\n\t"
        "D_%=:\n\t}"
        :: "r"(m), "r"(parity) : "memory");
}
__device__ __forceinline__ void mbar_arrive(uint32_t m) {
    asm volatile("mbarrier.arrive.shared.b64 _, [%0];" :: "r"(m) : "memory");
}
__device__ __forceinline__ void mbar_expect_tx(uint32_t m, uint32_t bytes) {
    asm volatile("mbarrier.arrive.expect_tx.shared.b64 _, [%0], %1;"
                 :: "r"(m), "r"(bytes) : "memory");
}
__device__ __forceinline__ void bulk_g2s(uint32_t dst, const void* src, uint32_t bytes,
                                         uint32_t mbar) {
    asm volatile(
        "cp.async.bulk.shared::cluster.global.mbarrier::complete_tx::bytes [%0], [%1], %2, [%3];"
        :: "r"(dst), "l"(src), "r"(bytes), "r"(mbar) : "memory");
}
__device__ __forceinline__ void ldsm_x4(uint32_t& r0, uint32_t& r1, uint32_t& r2, uint32_t& r3,
                                        uint32_t addr) {
    asm volatile("ldmatrix.sync.aligned.m8n8.x4.shared.b16 {%0,%1,%2,%3}, [%4];"
                 : "=r"(r0), "=r"(r1), "=r"(r2), "=r"(r3) : "r"(addr));
}
__device__ __forceinline__ void mma16816(float* c, const uint32_t* a, const uint32_t* b) {
    asm volatile(
        "mma.sync.aligned.m16n8k16.row.col.f32.bf16.bf16.f32 "
        "{%0,%1,%2,%3}, {%4,%5,%6,%7}, {%8,%9}, {%0,%1,%2,%3};"
        : "+f"(c[0]), "+f"(c[1]), "+f"(c[2]), "+f"(c[3])
        : "r"(a[0]), "r"(a[1]), "r"(a[2]), "r"(a[3]), "r"(b[0]), "r"(b[1]));
}
// combined-layout byte offset of the HI element (row, col) within a tile;
// the matching LO element is at +8192.
__device__ __forceinline__ uint32_t blk2_off(int r128, int col) {
    return (uint32_t)(col >> 5) * CHUNK_BYTES + swz64((uint32_t)(r128*64 + (col & 31)*2));
}
__device__ __forceinline__ void spin_ge(volatile unsigned int* f, unsigned int tgt) {
    while (*f < tgt) __nanosleep(64);
}

// ---------------- prep kernels ----------------
__global__ __launch_bounds__(256)
void v2_kernel(const float* __restrict__ Wk, const float* __restrict__ bq,
               float* __restrict__ v2)
{
    const int lane = threadIdx.x & 31;
    const int wrow = blockIdx.x * 8 + (threadIdx.x >> 5);
    float s = 0.0f;
    #pragma unroll
    for (int i = 0; i < 16; i++) {
        int d = i*32 + lane;
        s += Wk[(size_t)wrow*D_ + d] * bq[d];
    }
    #pragma unroll
    for (int o = 16; o > 0; o >>= 1) s += __shfl_xor_sync(0xffffffffu, s, o);
    if (lane == 0) v2[wrow] = s;
}

// warp-per-row split into combined hi|lo blocked layout + rk
__global__ __launch_bounds__(256)
void split_x_rk_kernel(const float* __restrict__ in, const float* __restrict__ v2,
                       __nv_bfloat16* __restrict__ xc, float* __restrict__ rk)
{
    const int lane = threadIdx.x & 31;
    const int row  = blockIdx.x * 8 + (threadIdx.x >> 5);
    const float4* src = reinterpret_cast<const float4*>(in) + (size_t)row * (D_/4);
    const float4* w4  = reinterpret_cast<const float4*>(v2);
    const size_t tbase = (size_t)(row >> 7) * TILE_STRIDE;
    const int r128 = row & 127;
    float local = 0.0f;
    #pragma unroll
    for (int j = 0; j < 4; j++) {
        const int c4 = j*32 + lane;            // float4 index within row
        float4 v = src[c4];
        float4 w = w4[c4];
        local += v.x*w.x + v.y*w.y + v.z*w.z + v.w*w.w;
        __nv_bfloat16 h[4], l[4];
        h[0] = __float2bfloat16(v.x); l[0] = __float2bfloat16(v.x - __bfloat162float(h[0]));
        h[1] = __float2bfloat16(v.y); l[1] = __float2bfloat16(v.y - __bfloat162float(h[1]));
        h[2] = __float2bfloat16(v.z); l[2] = __float2bfloat16(v.z - __bfloat162float(h[2]));
        h[3] = __float2bfloat16(v.w); l[3] = __float2bfloat16(v.w - __bfloat162float(h[3]));
        const uint32_t off = blk2_off(r128, c4*4);
        *reinterpret_cast<uint2*>((char*)xc + tbase + off)        = *reinterpret_cast<uint2*>(h);
        *reinterpret_cast<uint2*>((char*)xc + tbase + off + 8192) = *reinterpret_cast<uint2*>(l);
    }
    #pragma unroll
    for (int o = 16; o > 0; o >>= 1) local += __shfl_xor_sync(0xffffffffu, local, o);
    if (lane == 0) rk[row] = local * EXP2_SCALE;
}

__global__ __launch_bounds__(256)
void m2t_kernel(const float* __restrict__ Wk, const float* __restrict__ Wq,
                __nv_bfloat16* __restrict__ m2c)
{
    __shared__ float sk[32][33];
    __shared__ float sq[32][33];
    const int tid = threadIdx.x;
    const int g0 = blockIdx.y * 32, f0 = blockIdx.x * 32;
    const int ty = tid >> 4, tx = tid & 15;

    float acc[2][2] = {{0.f,0.f},{0.f,0.f}};
    for (int d0 = 0; d0 < D_; d0 += 32) {
        #pragma unroll
        for (int p = 0; p < 4; p++) {
            int e = p*256 + tid;
            int r = e >> 5, c = e & 31;
            sk[r][c] = Wk[(size_t)(g0+r)*D_ + d0 + c];
            sq[r][c] = Wq[(size_t)(f0+r)*D_ + d0 + c];
        }
        __syncthreads();
        #pragma unroll
        for (int d = 0; d < 32; d++) {
            float k0v = sk[2*ty][d],   k1v = sk[2*ty+1][d];
            float q0v = sq[2*tx][d],   q1v = sq[2*tx+1][d];
            acc[0][0] = fmaf(k0v, q0v, acc[0][0]);
            acc[0][1] = fmaf(k0v, q1v, acc[0][1]);
            acc[1][0] = fmaf(k1v, q0v, acc[1][0]);
            acc[1][1] = fmaf(k1v, q1v, acc[1][1]);
        }
        __syncthreads();
    }
    #pragma unroll
    for (int i = 0; i < 2; i++)
        #pragma unroll
        for (int j = 0; j < 2; j++) {
            float v = acc[i][j];
            __nv_bfloat16 h = __float2bfloat16(v);
            __nv_bfloat16 l = __float2bfloat16(v - __bfloat162float(h));
            int g = g0 + 2*ty + i;
            int f = f0 + 2*tx + j;
            size_t tbase = (size_t)(g >> 7) * TILE_STRIDE;
            uint32_t off = blk2_off(g & 127, f);
            *reinterpret_cast<__nv_bfloat16*>((char*)m2c + tbase + off)        = h;
            *reinterpret_cast<__nv_bfloat16*>((char*)m2c + tbase + off + 8192) = l;
        }
}

// ---------------- fused proj+scores+softmax NT GEMM ----------------
__global__ __launch_bounds__(256, 2)
void fused_gemm_kernel(const __nv_bfloat16* __restrict__ xc,
                       const __nv_bfloat16* __restrict__ m2c,
                       __nv_bfloat16* __restrict__ uc,
                       const float* __restrict__ rk,
                       float* __restrict__ outF,
                       float* __restrict__ psum,
                       unsigned int* uflag,
                       unsigned int* rcnt,
                       unsigned int* scnt,
                       unsigned int* srd)
{
    extern __shared__ char smem_raw[];
    const uint32_t sb = (smem_u32(smem_raw) + 1023u) & ~1023u;
    __shared__ float s_rowsum[128][4];
    __shared__ float s_inv[128];

    const int id     = blockIdx.x;
    const bool isProj = (id < N_PROJ_CTAS);
    const int tid    = threadIdx.x;
    const int lane   = tid & 31;
    const int wid    = tid >> 5;
    const int warp_m = wid & 1;
    const int warp_n = wid >> 1;

    int atile, btile, arow0, ncol0, sbx = 0, sbz = 0;
    const __nv_bfloat16 *aT, *bT;
    if (isProj) {
        const int bx = id & 3, by = id >> 2;
        atile = by; btile = bx;
        arow0 = by * BM; ncol0 = bx * BN;
        aT = xc;  bT = m2c;
    } else {
        const int sid = id - N_PROJ_CTAS;
        sbx = sid & 15;
        const int sby = (sid >> 4) & 15;
        sbz = sid >> 8;
        atile = sbz * 16 + sby;
        btile = sbz * 16 + sbx;
        arow0 = atile * BM; ncol0 = sbx * BN;
        aT = uc;  bT = xc;
    }
    const char* aB = (const char*)aT + (size_t)atile * TILE_STRIDE;
    const char* bB = (const char*)bT + (size_t)btile * TILE_STRIDE;
    const float* rkb = rk + (size_t)sbz * S_;

    if (tid == 0) {
        #pragma unroll
        for (int s = 0; s < NSTAGE; s++) {
            mbar_init(sb + s*8, 1);
            mbar_init(sb + 24 + s*8, 8);
        }
    }
    __syncthreads();

    if (tid == 0) {
        if (!isProj) {
            spin_ge(uflag + atile, 4u);
            __threadfence();
            unsigned int old = atomicInc(&rcnt[atile], 15u);
            if (old == 15u) uflag[atile] = 0u;
        }
        #pragma unroll
        for (int i = 0; i < 2; i++) {
            uint32_t st = sb + 1024 + i*STAGE_BYTES;
            uint32_t mb = sb + i*8;
            mbar_expect_tx(mb, STAGE_BYTES);
            bulk_g2s(st + STG_A, aB + (size_t)i*CHUNK_BYTES, CHUNK_BYTES, mb);
            bulk_g2s(st + STG_B, bB + (size_t)i*CHUNK_BYTES, CHUNK_BYTES, mb);
        }
    }

    const int laneR = lane & 15;
    const uint32_t laneC = (uint32_t)(lane >> 4) * 16;
    const uint32_t xorM  = (uint32_t)(laneR & 6) << 3;
    const uint32_t aBase = (uint32_t)(warp_m*64 + laneR) * 64;
    const uint32_t bBase = (uint32_t)(warp_n*32 + laneR) * 64;

    float acc[4][4][4];
    #pragma unroll
    for (int i = 0; i < 4; i++)
        #pragma unroll
        for (int j = 0; j < 4; j++)
            #pragma unroll
            for (int k = 0; k < 4; k++) acc[i][j][k] = 0.0f;

    int stage_c = 0;
    for (int c = 0; c < NCHUNK; c++) {
        mbar_wait(sb + stage_c*8, (c/NSTAGE) & 1);

        // rotating producer: chunk c+2 issued by lane 0 of warp (c+2)&7
        if (lane == 0 && wid == ((c + 2) & 7) && c + 2 < NCHUNK) {
            const int i = c + 2;
            int si = stage_c + 2; if (si >= NSTAGE) si -= NSTAGE;
            if (i >= NSTAGE)
                mbar_wait(sb + 24 + si*8, ((i/NSTAGE) - 1) & 1);
            uint32_t st = sb + 1024 + si*STAGE_BYTES;
            uint32_t mb = sb + si*8;
            mbar_expect_tx(mb, STAGE_BYTES);
            bulk_g2s(st + STG_A, aB + (size_t)i*CHUNK_BYTES, CHUNK_BYTES, mb);
            bulk_g2s(st + STG_B, bB + (size_t)i*CHUNK_BYTES, CHUNK_BYTES, mb);
        }

        const uint32_t stage = sb + 1024 + stage_c*STAGE_BYTES;
        #pragma unroll
        for (int kk = 0; kk < 2; kk++) {
            const uint32_t kbx = ((uint32_t)kk*32 + laneC) ^ xorM;

            uint32_t bhiF[4][2], bloF[4][2];
            #pragma unroll
            for (int g = 0; g < 2; g++) {
                uint32_t off = bBase + (uint32_t)g*1024 + kbx;
                uint32_t t0, t1, t2, t3;
                ldsm_x4(t0, t1, t2, t3, stage + STG_B + off);
                bhiF[2*g][0] = t0; bhiF[2*g][1] = t2; bhiF[2*g+1][0] = t1; bhiF[2*g+1][1] = t3;
                ldsm_x4(t0, t1, t2, t3, stage + STG_B + 8192 + off);
                bloF[2*g][0] = t0; bloF[2*g][1] = t2; bloF[2*g+1][0] = t1; bloF[2*g+1][1] = t3;
            }
            uint32_t ahiF[2][4], aloF[2][4];
            {
                uint32_t off = aBase + kbx;
                ldsm_x4(ahiF[0][0], ahiF[0][1], ahiF[0][2], ahiF[0][3], stage + STG_A + off);
                ldsm_x4(aloF[0][0], aloF[0][1], aloF[0][2], aloF[0][3], stage + STG_A + 8192 + off);
            }
            #pragma unroll
            for (int mf = 0; mf < 4; mf++) {
                const int cur = mf & 1, nxt = cur ^ 1;
                if (mf < 3) {
                    uint32_t off = aBase + (uint32_t)(mf+1)*1024 + kbx;
                    ldsm_x4(ahiF[nxt][0], ahiF[nxt][1], ahiF[nxt][2], ahiF[nxt][3],
                            stage + STG_A + off);
                    ldsm_x4(aloF[nxt][0], aloF[nxt][1], aloF[nxt][2], aloF[nxt][3],
                            stage + STG_A + 8192 + off);
                }
                if (kk == 1 && mf == 3 && lane == 0)
                    mbar_arrive(sb + 24 + stage_c*8);
                #pragma unroll
                for (int nf = 0; nf < 4; nf++)
                    mma16816(acc[mf][nf], ahiF[cur], bhiF[nf]);
                #pragma unroll
                for (int nf = 0; nf < 4; nf++)
                    mma16816(acc[mf][nf], ahiF[cur], bloF[nf]);
                #pragma unroll
                for (int nf = 0; nf < 4; nf++)
                    mma16816(acc[mf][nf], aloF[cur], bhiF[nf]);
            }
        }
        stage_c++; if (stage_c >= NSTAGE) stage_c -= NSTAGE;
    }

    const int g = lane >> 2, q = lane & 3;

    if (!isProj) {
        float rs[8];
        #pragma unroll
        for (int i = 0; i < 8; i++) rs[i] = 0.0f;
        #pragma unroll
        for (int mf = 0; mf < 4; mf++) {
            #pragma unroll
            for (int nf = 0; nf < 4; nf++) {
                const int col = ncol0 + warp_n*32 + nf*8 + q*2;
                const float r0 = __ldg(&rkb[col]);
                const float r1 = __ldg(&rkb[col+1]);
                acc[mf][nf][0] = exp2f(fmaf(acc[mf][nf][0], EXP2_SCALE, r0));
                acc[mf][nf][1] = exp2f(fmaf(acc[mf][nf][1], EXP2_SCALE, r1));
                acc[mf][nf][2] = exp2f(fmaf(acc[mf][nf][2], EXP2_SCALE, r0));
                acc[mf][nf][3] = exp2f(fmaf(acc[mf][nf][3], EXP2_SCALE, r1));
                rs[mf*2 + 0] += acc[mf][nf][0] + acc[mf][nf][1];
                rs[mf*2 + 1] += acc[mf][nf][2] + acc[mf][nf][3];
            }
        }
        #pragma unroll
        for (int i = 0; i < 8; i++) {
            rs[i] += __shfl_xor_sync(0xffffffffu, rs[i], 1);
            rs[i] += __shfl_xor_sync(0xffffffffu, rs[i], 2);
        }
        if (q == 0) {
            #pragma unroll
            for (int i = 0; i < 8; i++)
                s_rowsum[warp_m*64 + (i>>1)*16 + (i&1)*8 + g][warp_n] = rs[i];
        }
        __syncthreads();
        if (tid < 128) {
            float s = s_rowsum[tid][0] + s_rowsum[tid][1] + s_rowsum[tid][2] + s_rowsum[tid][3];
            psum[((size_t)arow0 + tid)*NT_ + sbx] = s;
        }

        __threadfence();
        __syncthreads();
        if (tid == 0) {
            atomicAdd(&scnt[atile], 1u);
            spin_ge(scnt + atile, (unsigned)NT_);
        }
        __syncthreads();
        __threadfence();
        if (tid < 128) {
            const float* pr = &psum[((size_t)arow0 + tid) * NT_];
            float s = 0.0f;
            #pragma unroll
            for (int t = 0; t < NT_; t++) s += pr[t];
            s_inv[tid] = 1.0f / s;
        }
        __syncthreads();

        #pragma unroll
        for (int mf = 0; mf < 4; mf++) {
            const int r0 = warp_m*64 + mf*16 + g;
            const float iv0 = s_inv[r0];
            const float iv1 = s_inv[r0 + 8];
            const size_t grow = (size_t)arow0 + r0;
            #pragma unroll
            for (int nf = 0; nf < 4; nf++) {
                const int col = ncol0 + warp_n*32 + nf*8 + q*2;
                *reinterpret_cast<float2*>(&outF[grow*S_ + col]) =
                    make_float2(acc[mf][nf][0]*iv0, acc[mf][nf][1]*iv0);
                *reinterpret_cast<float2*>(&outF[(grow+8)*S_ + col]) =
                    make_float2(acc[mf][nf][2]*iv1, acc[mf][nf][3]*iv1);
            }
        }

        if (tid == 0) {
            unsigned int old = atomicInc(&srd[atile], 15u);
            if (old == 15u) scnt[atile] = 0u;
        }
    } else {
        char* ob = (char*)uc + (size_t)atile * TILE_STRIDE;
        #pragma unroll
        for (int mf = 0; mf < 4; mf++) {
            const int r0 = warp_m*64 + mf*16 + g;
            #pragma unroll
            for (int nf = 0; nf < 4; nf++) {
                const int col = ncol0 + warp_n*32 + nf*8 + q*2;
                float v0 = acc[mf][nf][0];
                float v1 = acc[mf][nf][1];
                float v2v = acc[mf][nf][2];
                float v3 = acc[mf][nf][3];
                __nv_bfloat162 h01, l01, h23, l23;
                h01.x = __float2bfloat16(v0); h01.y = __float2bfloat16(v1);
                l01.x = __float2bfloat16(v0 - __bfloat162float(h01.x));
                l01.y = __float2bfloat16(v1 - __bfloat162float(h01.y));
                h23.x = __float2bfloat16(v2v); h23.y = __float2bfloat16(v3);
                l23.x = __float2bfloat16(v2v - __bfloat162float(h23.x));
                l23.y = __float2bfloat16(v3 - __bfloat162float(h23.y));
                uint32_t o0 = blk2_off(r0,     col);
                uint32_t o1 = blk2_off(r0 + 8, col);
                *reinterpret_cast<__nv_bfloat162*>(ob + o0)        = h01;
                *reinterpret_cast<__nv_bfloat162*>(ob + o0 + 8192) = l01;
                *reinterpret_cast<__nv_bfloat162*>(ob + o1)        = h23;
                *reinterpret_cast<__nv_bfloat162*>(ob + o1 + 8192) = l23;
            }
        }
        __threadfence();
        __syncthreads();
        if (tid == 0) atomicAdd(&uflag[atile], 1u);
    }
}

// ---------------- launcher ----------------
extern "C" void kernel_launch(void* const* d_in, const int* in_sizes, int n_in,
                              void* d_out, int out_size)
{
    const float* x  = (const float*)d_in[0];
    const float* Wq = (const float*)d_in[1];
    const float* bq = (const float*)d_in[2];
    const float* Wk = (const float*)d_in[3];
    float* out = (float*)d_out;

    __nv_bfloat16 *xcp, *m2cp, *ucp;
    float *v2p, *rkp, *pptr;
    unsigned int *uflagp, *urdp, *scntp, *srdp;
    cudaGetSymbolAddress((void**)&xcp,  g_x);
    cudaGetSymbolAddress((void**)&m2cp, g_m2);
    cudaGetSymbolAddress((void**)&ucp,  g_u);
    cudaGetSymbolAddress((void**)&v2p,  g_v2);
    cudaGetSymbolAddress((void**)&rkp,  g_rk);
    cudaGetSymbolAddress((void**)&pptr, g_psum);
    cudaGetSymbolAddress((void**)&uflagp, g_uflag);
    cudaGetSymbolAddress((void**)&urdp,   g_u_rd);
    cudaGetSymbolAddress((void**)&scntp,  g_scnt);
    cudaGetSymbolAddress((void**)&srdp,   g_srd);

    cudaFuncSetAttribute(fused_gemm_kernel, cudaFuncAttributeMaxDynamicSharedMemorySize, SMEM_DYN);

    // 1) preps
    v2_kernel<<<D_/8, 256>>>(Wk, bq, v2p);
    split_x_rk_kernel<<<B_*S_/8, 256>>>(x, v2p, xcp, rkp);
    dim3 mg(D_/32, D_/32);
    m2t_kernel<<<mg, 256>>>(Wk, Wq, m2cp);

    // 2) fused proj + scores + softmax (single output write)
    fused_gemm_kernel<<<N_PROJ_CTAS + S_/BN * S_/BM * B_, 256, SMEM_DYN>>>(
        xcp, m2cp, ucp, rkp, out, pptr, uflagp, urdp, scntp, srdp);
}